// round 1
// baseline (speedup 1.0000x reference)
#include <cuda_runtime.h>
#include <math.h>

#define HID 128
#define NMAX 50048
#define EMAX 1600000

// ---------------- device scratch (no allocations allowed) ----------------
__device__ float g_h[NMAX * HID];
__device__ float g_xl[NMAX * HID];
__device__ float g_xr[NMAX * HID];
__device__ float g_gamma[NMAX * HID];
__device__ float g_beta[NMAX * HID];
__device__ float g_s[EMAX * 4];
__device__ int   g_off[NMAX + 1];
__device__ int   g_cnt[NMAX];
__device__ int   g_csrc[EMAX];
__device__ int   g_cdst[EMAX];
__device__ int   g_ceid[EMAX];
__device__ int   g_viol[2];
__device__ int   g_maskmode;

__device__ __forceinline__ float gelu_f(float x) {
    return 0.5f * x * (1.0f + erff(x * 0.7071067811865476f));
}

// ---------------- utility kernels ----------------
__global__ void k_zero(int n) {
    int i = blockIdx.x * blockDim.x + threadIdx.x;
    if (i < n) g_cnt[i] = 0;
    if (i < 2) g_viol[i] = 0;
}

// detect serialization of is_fixed_mask: 0=int32, 1=float32, 2=uint8
__global__ void k_maskdetect(const int* m, int n) {
    int words = n >> 2;                 // safe under all 3 interpretations
    int lim = words < 8192 ? words : 8192;
    int vi = 0, vf = 0;
    for (int i = blockIdx.x * blockDim.x + threadIdx.x; i < lim;
         i += gridDim.x * blockDim.x) {
        int v = m[i];
        if (v != 0 && v != 1) vi = 1;
        if (v != 0 && v != 0x3F800000) vf = 1;
    }
    if (vi) atomicOr(&g_viol[0], 1);
    if (vf) atomicOr(&g_viol[1], 1);
}

__global__ void k_maskresolve() {
    g_maskmode = (g_viol[0] == 0) ? 0 : ((g_viol[1] == 0) ? 1 : 2);
}

__global__ void k_count(const int* ei, int e) {
    int i = blockIdx.x * blockDim.x + threadIdx.x;
    if (i < e) atomicAdd(&g_cnt[ei[e + i]], 1);
}

// single-block exclusive scan over g_cnt[0..n) -> g_off
__global__ void k_scan(int n) {
    __shared__ int sh[2][1024];
    __shared__ int carry;
    int t = threadIdx.x;
    if (t == 0) carry = 0;
    __syncthreads();
    for (int base = 0; base < n; base += 1024) {
        int i = base + t;
        int v = (i < n) ? g_cnt[i] : 0;
        int c0 = carry;
        sh[0][t] = v;
        __syncthreads();
        int pin = 0;
        #pragma unroll
        for (int off = 1; off < 1024; off <<= 1) {
            sh[pin ^ 1][t] = sh[pin][t] + ((t >= off) ? sh[pin][t - off] : 0);
            __syncthreads();
            pin ^= 1;
        }
        int inc = sh[pin][t];
        if (i < n) g_off[i] = c0 + inc - v;
        __syncthreads();
        if (t == 1023) carry = c0 + sh[pin][1023];
        __syncthreads();
    }
    if (t == 0) g_off[n] = carry;
}

__global__ void k_scatter(const int* ei, int e) {
    int i = blockIdx.x * blockDim.x + threadIdx.x;
    if (i >= e) return;
    int s = ei[i], d = ei[e + i];
    int pos = g_off[d] + atomicAdd(&g_cnt[d], 1);
    g_csrc[pos] = s;
    g_cdst[pos] = d;
    g_ceid[pos] = i;
}

// ---------------- encoder + FiLM (one warp per node) ----------------
__global__ void k_prep(const float* __restrict__ x, const float* __restrict__ tmp,
                       const float* __restrict__ encW, const float* __restrict__ encB,
                       const float* __restrict__ encG, const float* __restrict__ encBe,
                       const float* __restrict__ fW1, const float* __restrict__ fb1,
                       const float* __restrict__ fW2, const float* __restrict__ fb2,
                       int n) {
    extern __shared__ float sm[];
    float* sEncW = sm;            // 768
    float* sW1   = sm + 768;      // 64
    float* sB1   = sm + 832;      // 64
    float* sB2   = sm + 896;      // 256
    float* sW2   = sm + 1152;     // 16384
    float* sT1   = sm + 17536;    // 512 (8 warps x 64)
    int tid = threadIdx.x;
    for (int i = tid; i < 768; i += blockDim.x) sEncW[i] = encW[i];
    for (int i = tid; i < 64; i += blockDim.x) { sW1[i] = fW1[i]; sB1[i] = fb1[i]; }
    for (int i = tid; i < 256; i += blockDim.x) sB2[i] = fb2[i];
    for (int i = tid; i < 16384; i += blockDim.x) sW2[i] = fW2[i];
    __syncthreads();
    int warp = tid >> 5, lane = tid & 31;
    for (int i = blockIdx.x * 8 + warp; i < n; i += gridDim.x * 8) {
        float xv[6];
        #pragma unroll
        for (int j = 0; j < 6; j++) xv[j] = x[i * 6 + j];
        float y[4];
        #pragma unroll
        for (int h = 0; h < 4; h++) {
            int k = h * 32 + lane;
            float a = encB[k];
            #pragma unroll
            for (int j = 0; j < 6; j++) a += xv[j] * sEncW[j * 128 + k];
            y[h] = a;
        }
        float s1 = y[0] + y[1] + y[2] + y[3];
        float s2 = y[0]*y[0] + y[1]*y[1] + y[2]*y[2] + y[3]*y[3];
        #pragma unroll
        for (int o = 16; o > 0; o >>= 1) {
            s1 += __shfl_xor_sync(0xFFFFFFFFu, s1, o);
            s2 += __shfl_xor_sync(0xFFFFFFFFu, s2, o);
        }
        float mean = s1 * (1.0f / 128.0f);
        float var  = s2 * (1.0f / 128.0f) - mean * mean;
        float inv  = rsqrtf(var + 1e-5f);
        #pragma unroll
        for (int h = 0; h < 4; h++) {
            int k = h * 32 + lane;
            float v = (y[h] - mean) * inv * encG[k] + encBe[k];
            g_h[i * 128 + k] = gelu_f(v);
        }
        // FiLM
        float tm = tmp[i];
        #pragma unroll
        for (int c = 0; c < 2; c++) {
            int j = lane + 32 * c;
            sT1[warp * 64 + j] = gelu_f(tm * sW1[j] + sB1[j]);
        }
        __syncwarp();
        float f[8];
        #pragma unroll
        for (int c = 0; c < 8; c++) f[c] = sB2[lane + 32 * c];
        for (int j = 0; j < 64; j++) {
            float t = sT1[warp * 64 + j];
            #pragma unroll
            for (int c = 0; c < 8; c++) f[c] += t * sW2[j * 256 + lane + 32 * c];
        }
        #pragma unroll
        for (int c = 0; c < 4; c++) {
            g_gamma[i * 128 + lane + 32 * c] = f[c];
            g_beta[i * 128 + lane + 32 * c]  = f[c + 4];
        }
        __syncwarp();
    }
}

// ---------------- per-layer dual GEMM: xl = h@Wl+bl, xr = h@Wr+br ----------------
__global__ void k_gemm(const float* __restrict__ Wl, const float* __restrict__ blv,
                       const float* __restrict__ Wr, const float* __restrict__ brv,
                       int n) {
    extern __shared__ float sm[];
    float* sWl = sm;             // 16384 floats
    float* sWr = sm + 16384;     // 16384
    float* sA  = sm + 32768;     // 8192 (64 rows x 128)
    int tid = threadIdx.x;
    for (int i = tid; i < 4096; i += 256) {
        ((float4*)sWl)[i] = ((const float4*)Wl)[i];
        ((float4*)sWr)[i] = ((const float4*)Wr)[i];
    }
    int row0 = blockIdx.x * 64;
    for (int i = tid; i < 2048; i += 256) {
        int r = i >> 5, c4 = i & 31;
        int gr = row0 + r;
        float4 v = (gr < n) ? ((const float4*)g_h)[gr * 32 + c4]
                            : make_float4(0.f, 0.f, 0.f, 0.f);
        ((float4*)sA)[i] = v;
    }
    __syncthreads();
    int warp = tid >> 5, lane = tid & 31;
    float4 bL = ((const float4*)blv)[lane];
    float4 bR = ((const float4*)brv)[lane];
    float4 aL[8], aR[8];
    #pragma unroll
    for (int r = 0; r < 8; r++) { aL[r] = bL; aR[r] = bR; }
    const float4* sWl4 = (const float4*)sWl;
    const float4* sWr4 = (const float4*)sWr;
    #pragma unroll 4
    for (int k = 0; k < 128; k++) {
        float4 wl = sWl4[k * 32 + lane];
        float4 wr = sWr4[k * 32 + lane];
        #pragma unroll
        for (int r = 0; r < 8; r++) {
            float a = sA[(warp * 8 + r) * 128 + k];
            aL[r].x += a * wl.x; aL[r].y += a * wl.y;
            aL[r].z += a * wl.z; aL[r].w += a * wl.w;
            aR[r].x += a * wr.x; aR[r].y += a * wr.y;
            aR[r].z += a * wr.z; aR[r].w += a * wr.w;
        }
    }
    #pragma unroll
    for (int r = 0; r < 8; r++) {
        int gr = row0 + warp * 8 + r;
        if (gr < n) {
            ((float4*)g_xl)[gr * 32 + lane] = aL[r];
            ((float4*)g_xr)[gr * 32 + lane] = aR[r];
        }
    }
}

// ---------------- edge attention scores (one warp per CSR edge) ----------------
__global__ void k_edge(const float* __restrict__ edge_attr,
                       const float* __restrict__ We, const float* __restrict__ att,
                       int e) {
    __shared__ float sWe[512];
    __shared__ float sAtt[128];
    int tid = threadIdx.x;
    for (int i = tid; i < 512; i += 256) sWe[i] = We[i];
    if (tid < 128) sAtt[tid] = att[tid];
    __syncthreads();
    int warp = tid >> 5, lane = tid & 31;
    for (int j = blockIdx.x * 8 + warp; j < e; j += gridDim.x * 8) {
        int src = g_csrc[j], dst = g_cdst[j], eid = g_ceid[j];
        float4 ea = ((const float4*)edge_attr)[eid];
        float sv[4];
        #pragma unroll
        for (int h = 0; h < 4; h++) {
            int k = h * 32 + lane;
            float m = g_xl[src * 128 + k] + g_xr[dst * 128 + k]
                    + ea.x * sWe[k] + ea.y * sWe[128 + k]
                    + ea.z * sWe[256 + k] + ea.w * sWe[384 + k];
            m = (m > 0.f) ? m : 0.2f * m;
            float v = m * sAtt[k];
            #pragma unroll
            for (int o = 16; o > 0; o >>= 1) v += __shfl_xor_sync(0xFFFFFFFFu, v, o);
            sv[h] = v;
        }
        if (lane == 0)
            ((float4*)g_s)[j] = make_float4(sv[0], sv[1], sv[2], sv[3]);
    }
}

// ---------------- node: softmax + aggregate + FiLM + LN + GELU + residual ----------------
__global__ void k_node(const float* __restrict__ cb, const float* __restrict__ lng,
                       const float* __restrict__ lnb, int n) {
    int tid = threadIdx.x;
    int warp = tid >> 5, lane = tid & 31;
    int i = blockIdx.x * 8 + warp;
    if (i >= n) return;
    int beg = g_off[i], end = g_off[i + 1];
    const float4* s4 = (const float4*)g_s;
    float4 mx = make_float4(-1e30f, -1e30f, -1e30f, -1e30f);
    for (int j = beg + lane; j < end; j += 32) {
        float4 s = s4[j];
        mx.x = fmaxf(mx.x, s.x); mx.y = fmaxf(mx.y, s.y);
        mx.z = fmaxf(mx.z, s.z); mx.w = fmaxf(mx.w, s.w);
    }
    #pragma unroll
    for (int o = 16; o > 0; o >>= 1) {
        mx.x = fmaxf(mx.x, __shfl_xor_sync(0xFFFFFFFFu, mx.x, o));
        mx.y = fmaxf(mx.y, __shfl_xor_sync(0xFFFFFFFFu, mx.y, o));
        mx.z = fmaxf(mx.z, __shfl_xor_sync(0xFFFFFFFFu, mx.z, o));
        mx.w = fmaxf(mx.w, __shfl_xor_sync(0xFFFFFFFFu, mx.w, o));
    }
    float4 se = make_float4(0.f, 0.f, 0.f, 0.f);
    for (int j = beg + lane; j < end; j += 32) {
        float4 s = s4[j];
        se.x += __expf(s.x - mx.x); se.y += __expf(s.y - mx.y);
        se.z += __expf(s.z - mx.z); se.w += __expf(s.w - mx.w);
    }
    #pragma unroll
    for (int o = 16; o > 0; o >>= 1) {
        se.x += __shfl_xor_sync(0xFFFFFFFFu, se.x, o);
        se.y += __shfl_xor_sync(0xFFFFFFFFu, se.y, o);
        se.z += __shfl_xor_sync(0xFFFFFFFFu, se.z, o);
        se.w += __shfl_xor_sync(0xFFFFFFFFu, se.w, o);
    }
    float4 inv;
    inv.x = 1.f / (se.x + 1e-16f); inv.y = 1.f / (se.y + 1e-16f);
    inv.z = 1.f / (se.z + 1e-16f); inv.w = 1.f / (se.w + 1e-16f);
    float acc0 = 0.f, acc1 = 0.f, acc2 = 0.f, acc3 = 0.f;
    for (int j = beg; j < end; j++) {
        float4 s = s4[j];
        int src = g_csrc[j];
        float w0 = __expf(s.x - mx.x) * inv.x;
        float w1 = __expf(s.y - mx.y) * inv.y;
        float w2 = __expf(s.z - mx.z) * inv.z;
        float w3 = __expf(s.w - mx.w) * inv.w;
        const float* xl = &g_xl[src * 128];
        acc0 += w0 * xl[lane];
        acc1 += w1 * xl[32 + lane];
        acc2 += w2 * xl[64 + lane];
        acc3 += w3 * xl[96 + lane];
    }
    float y[4];
    y[0] = acc0; y[1] = acc1; y[2] = acc2; y[3] = acc3;
    #pragma unroll
    for (int h = 0; h < 4; h++) {
        int k = h * 32 + lane;
        float hc = y[h] + cb[k];
        y[h] = g_gamma[i * 128 + k] * hc + g_beta[i * 128 + k];
    }
    float s1 = y[0] + y[1] + y[2] + y[3];
    float s2 = y[0]*y[0] + y[1]*y[1] + y[2]*y[2] + y[3]*y[3];
    #pragma unroll
    for (int o = 16; o > 0; o >>= 1) {
        s1 += __shfl_xor_sync(0xFFFFFFFFu, s1, o);
        s2 += __shfl_xor_sync(0xFFFFFFFFu, s2, o);
    }
    float mean = s1 * (1.0f / 128.0f);
    float var  = s2 * (1.0f / 128.0f) - mean * mean;
    float ivs  = rsqrtf(var + 1e-5f);
    #pragma unroll
    for (int h = 0; h < 4; h++) {
        int k = h * 32 + lane;
        float v = (y[h] - mean) * ivs * lng[k] + lnb[k];
        g_h[i * 128 + k] = gelu_f(v) + g_h[i * 128 + k];
    }
}

// ---------------- decoder + mask + output ----------------
__global__ void k_dec(const float* __restrict__ W1, const float* __restrict__ b1,
                      const float* __restrict__ W2, const float* __restrict__ b2,
                      const float* __restrict__ x, const void* __restrict__ mask,
                      float* __restrict__ out, int n, int out_size) {
    __shared__ float sW1[8192];
    __shared__ float sW2[128];
    __shared__ float sb1v[64];
    __shared__ float sb2v[2];
    __shared__ float sH[8][128];
    int tid = threadIdx.x;
    for (int i = tid; i < 8192; i += 256) sW1[i] = W1[i];
    if (tid < 128) sW2[tid] = W2[tid];
    if (tid < 64) sb1v[tid] = b1[tid];
    if (tid < 2) sb2v[tid] = b2[tid];
    __syncthreads();
    int warp = tid >> 5, lane = tid & 31;
    int mode = g_maskmode;
    for (int i = blockIdx.x * 8 + warp; i < n; i += gridDim.x * 8) {
        #pragma unroll
        for (int h = 0; h < 4; h++) sH[warp][h * 32 + lane] = g_h[i * 128 + h * 32 + lane];
        __syncwarp();
        float a0 = sb1v[lane], a1 = sb1v[lane + 32];
        for (int k = 0; k < 128; k++) {
            float hv = sH[warp][k];
            a0 += hv * sW1[k * 64 + lane];
            a1 += hv * sW1[k * 64 + lane + 32];
        }
        float t0 = gelu_f(a0), t1 = gelu_f(a1);
        float d0 = t0 * sW2[lane * 2]     + t1 * sW2[(lane + 32) * 2];
        float d1 = t0 * sW2[lane * 2 + 1] + t1 * sW2[(lane + 32) * 2 + 1];
        #pragma unroll
        for (int o = 16; o > 0; o >>= 1) {
            d0 += __shfl_xor_sync(0xFFFFFFFFu, d0, o);
            d1 += __shfl_xor_sync(0xFFFFFFFFu, d1, o);
        }
        if (lane == 0) {
            d0 += sb2v[0]; d1 += sb2v[1];
            int fixed;
            if (mode == 0)      fixed = ((const int*)mask)[i] != 0;
            else if (mode == 1) fixed = ((const float*)mask)[i] != 0.f;
            else                fixed = ((const unsigned char*)mask)[i] != 0;
            if (fixed) { d0 = 0.f; d1 = 0.f; }
            out[i * 2]     = x[i * 6]     + d0;
            out[i * 2 + 1] = x[i * 6 + 1] + d1;
            if (out_size >= 4 * n) {
                out[2 * n + i * 2]     = d0;
                out[2 * n + i * 2 + 1] = d1;
            }
        }
        __syncwarp();
    }
}

// ---------------- launch ----------------
extern "C" void kernel_launch(void* const* d_in, const int* in_sizes, int n_in,
                              void* d_out, int out_size) {
    const float* x    = (const float*)d_in[0];
    const int*   ei   = (const int*)d_in[1];
    const float* ea   = (const float*)d_in[2];
    const float* tmp  = (const float*)d_in[3];
    const void*  mask = d_in[4];
    const float* encW = (const float*)d_in[5];
    const float* encB = (const float*)d_in[6];
    const float* encG = (const float*)d_in[7];
    const float* encBe= (const float*)d_in[8];
    const float* fW1  = (const float*)d_in[9];
    const float* fb1  = (const float*)d_in[10];
    const float* fW2  = (const float*)d_in[11];
    const float* fb2  = (const float*)d_in[12];
    const float* Wl   = (const float*)d_in[13];
    const float* bl   = (const float*)d_in[14];
    const float* Wr   = (const float*)d_in[15];
    const float* br   = (const float*)d_in[16];
    const float* We   = (const float*)d_in[17];
    const float* att  = (const float*)d_in[18];
    const float* cb   = (const float*)d_in[19];
    const float* lng  = (const float*)d_in[20];
    const float* lnb  = (const float*)d_in[21];
    const float* dW1  = (const float*)d_in[22];
    const float* db1  = (const float*)d_in[23];
    const float* dW2  = (const float*)d_in[24];
    const float* db2  = (const float*)d_in[25];
    float* out = (float*)d_out;

    int n = in_sizes[0] / 6;
    int e = in_sizes[2] / 4;

    cudaFuncSetAttribute(k_prep, cudaFuncAttributeMaxDynamicSharedMemorySize, 73728);
    cudaFuncSetAttribute(k_gemm, cudaFuncAttributeMaxDynamicSharedMemorySize, 166912);

    // CSR build + mask detection
    k_zero<<<(n + 255) / 256, 256>>>(n);
    k_maskdetect<<<32, 256>>>((const int*)mask, n);
    k_maskresolve<<<1, 1>>>();
    k_count<<<(e + 255) / 256, 256>>>(ei, e);
    k_scan<<<1, 1024>>>(n);
    k_zero<<<(n + 255) / 256, 256>>>(n);
    k_scatter<<<(e + 255) / 256, 256>>>(ei, e);

    // encoder + FiLM
    k_prep<<<1536, 256, 72192>>>(x, tmp, encW, encB, encG, encBe,
                                 fW1, fb1, fW2, fb2, n);

    // 4 GATv2 layers
    for (int l = 0; l < 4; l++) {
        k_gemm<<<(n + 63) / 64, 256, 163840>>>(Wl + l * 16384, bl + l * 128,
                                               Wr + l * 16384, br + l * 128, n);
        k_edge<<<16384, 256>>>(ea, We + l * 512, att + l * 128, e);
        k_node<<<(n + 7) / 8, 256>>>(cb + l * 128, lng + l * 128, lnb + l * 128, n);
    }

    // decoder + output
    k_dec<<<1536, 256>>>(dW1, db1, dW2, db2, x, mask, out, n, out_size);
}

// round 2
// speedup vs baseline: 1.8360x; 1.8360x over previous
#include <cuda_runtime.h>
#include <math.h>

#define HID 128
#define NMAX 50048
#define EMAX 1600000

// ---------------- device scratch ----------------
__device__ float  g_h[NMAX * HID];
__device__ float  g_xl[NMAX * HID];
__device__ float  g_xr[NMAX * HID];
__device__ float  g_gamma[NMAX * HID];
__device__ float  g_beta[NMAX * HID];
__device__ float4 g_ea[EMAX];
__device__ int    g_off[NMAX + 1];
__device__ int    g_cnt[NMAX];
__device__ int    g_csrc[EMAX];
__device__ int    g_viol[2];
__device__ int    g_maskmode;

__device__ __forceinline__ float gelu_f(float x) {
    return 0.5f * x * (1.0f + erff(x * 0.7071067811865476f));
}

// packed fp32x2 helpers (Blackwell)
__device__ __forceinline__ unsigned long long fma2(unsigned long long a,
                                                   unsigned long long b,
                                                   unsigned long long c) {
    unsigned long long d;
    asm("fma.rn.f32x2 %0, %1, %2, %3;" : "=l"(d) : "l"(a), "l"(b), "l"(c));
    return d;
}
__device__ __forceinline__ unsigned long long pack2(float x) {
    unsigned long long d;
    asm("mov.b64 %0, {%1, %1};" : "=l"(d) : "f"(x));
    return d;
}
__device__ __forceinline__ unsigned long long pack2f(float a, float b) {
    unsigned long long d;
    asm("mov.b64 %0, {%1, %2};" : "=l"(d) : "f"(a), "f"(b));
    return d;
}
__device__ __forceinline__ float2 unpack2(unsigned long long v) {
    float2 r;
    asm("mov.b64 {%0, %1}, %2;" : "=f"(r.x), "=f"(r.y) : "l"(v));
    return r;
}

// ---------------- utility kernels ----------------
__global__ void k_zero(int n) {
    int i = blockIdx.x * blockDim.x + threadIdx.x;
    if (i < n) g_cnt[i] = 0;
    if (i < 2) g_viol[i] = 0;
}

// detect serialization of is_fixed_mask: 0=int32, 1=float32, 2=uint8
__global__ void k_maskdetect(const int* m, int n) {
    int words = n >> 2;
    int lim = words < 8192 ? words : 8192;
    int vi = 0, vf = 0;
    for (int i = blockIdx.x * blockDim.x + threadIdx.x; i < lim;
         i += gridDim.x * blockDim.x) {
        int v = m[i];
        if (v != 0 && v != 1) vi = 1;
        if (v != 0 && v != 0x3F800000) vf = 1;
    }
    if (vi) atomicOr(&g_viol[0], 1);
    if (vf) atomicOr(&g_viol[1], 1);
}

__global__ void k_maskresolve() {
    g_maskmode = (g_viol[0] == 0) ? 0 : ((g_viol[1] == 0) ? 1 : 2);
}

__global__ void k_count(const int* ei, int e) {
    int i = blockIdx.x * blockDim.x + threadIdx.x;
    if (i < e) atomicAdd(&g_cnt[ei[e + i]], 1);
}

// single-block exclusive scan over g_cnt[0..n) -> g_off
__global__ void k_scan(int n) {
    __shared__ int sh[2][1024];
    __shared__ int carry;
    int t = threadIdx.x;
    if (t == 0) carry = 0;
    __syncthreads();
    for (int base = 0; base < n; base += 1024) {
        int i = base + t;
        int v = (i < n) ? g_cnt[i] : 0;
        int c0 = carry;
        sh[0][t] = v;
        __syncthreads();
        int pin = 0;
        #pragma unroll
        for (int off = 1; off < 1024; off <<= 1) {
            sh[pin ^ 1][t] = sh[pin][t] + ((t >= off) ? sh[pin][t - off] : 0);
            __syncthreads();
            pin ^= 1;
        }
        int inc = sh[pin][t];
        if (i < n) g_off[i] = c0 + inc - v;
        __syncthreads();
        if (t == 1023) carry = c0 + sh[pin][1023];
        __syncthreads();
    }
    if (t == 0) g_off[n] = carry;
}

__global__ void k_scatter(const int* ei, const float4* __restrict__ ea, int e) {
    int i = blockIdx.x * blockDim.x + threadIdx.x;
    if (i >= e) return;
    int s = ei[i], d = ei[e + i];
    int pos = g_off[d] + atomicAdd(&g_cnt[d], 1);
    g_csrc[pos] = s;
    g_ea[pos] = ea[i];
}

// ---------------- encoder + FiLM (one warp per node) ----------------
__global__ void k_prep(const float* __restrict__ x, const float* __restrict__ tmp,
                       const float* __restrict__ encW, const float* __restrict__ encB,
                       const float* __restrict__ encG, const float* __restrict__ encBe,
                       const float* __restrict__ fW1, const float* __restrict__ fb1,
                       const float* __restrict__ fW2, const float* __restrict__ fb2,
                       int n) {
    extern __shared__ float sm[];
    float* sEncW = sm;            // 768
    float* sW1   = sm + 768;      // 64
    float* sB1   = sm + 832;      // 64
    float* sB2   = sm + 896;      // 256
    float* sW2   = sm + 1152;     // 16384
    float* sT1   = sm + 17536;    // 512
    int tid = threadIdx.x;
    for (int i = tid; i < 768; i += blockDim.x) sEncW[i] = encW[i];
    for (int i = tid; i < 64; i += blockDim.x) { sW1[i] = fW1[i]; sB1[i] = fb1[i]; }
    for (int i = tid; i < 256; i += blockDim.x) sB2[i] = fb2[i];
    for (int i = tid; i < 16384; i += blockDim.x) sW2[i] = fW2[i];
    __syncthreads();
    int warp = tid >> 5, lane = tid & 31;
    for (int i = blockIdx.x * 8 + warp; i < n; i += gridDim.x * 8) {
        float xv[6];
        #pragma unroll
        for (int j = 0; j < 6; j++) xv[j] = x[i * 6 + j];
        float y[4];
        #pragma unroll
        for (int h = 0; h < 4; h++) {
            int k = h * 32 + lane;
            float a = encB[k];
            #pragma unroll
            for (int j = 0; j < 6; j++) a += xv[j] * sEncW[j * 128 + k];
            y[h] = a;
        }
        float s1 = y[0] + y[1] + y[2] + y[3];
        float s2 = y[0]*y[0] + y[1]*y[1] + y[2]*y[2] + y[3]*y[3];
        #pragma unroll
        for (int o = 16; o > 0; o >>= 1) {
            s1 += __shfl_xor_sync(0xFFFFFFFFu, s1, o);
            s2 += __shfl_xor_sync(0xFFFFFFFFu, s2, o);
        }
        float mean = s1 * (1.0f / 128.0f);
        float var  = s2 * (1.0f / 128.0f) - mean * mean;
        float inv  = rsqrtf(var + 1e-5f);
        #pragma unroll
        for (int h = 0; h < 4; h++) {
            int k = h * 32 + lane;
            float v = (y[h] - mean) * inv * encG[k] + encBe[k];
            g_h[i * 128 + k] = gelu_f(v);
        }
        float tm = tmp[i];
        #pragma unroll
        for (int c = 0; c < 2; c++) {
            int j = lane + 32 * c;
            sT1[warp * 64 + j] = gelu_f(tm * sW1[j] + sB1[j]);
        }
        __syncwarp();
        float f[8];
        #pragma unroll
        for (int c = 0; c < 8; c++) f[c] = sB2[lane + 32 * c];
        for (int j = 0; j < 64; j++) {
            float t = sT1[warp * 64 + j];
            #pragma unroll
            for (int c = 0; c < 8; c++) f[c] += t * sW2[j * 256 + lane + 32 * c];
        }
        #pragma unroll
        for (int c = 0; c < 4; c++) {
            g_gamma[i * 128 + lane + 32 * c] = f[c];
            g_beta[i * 128 + lane + 32 * c]  = f[c + 4];
        }
        __syncwarp();
    }
}

// ---------------- dual GEMM with packed f32x2: xl = h@Wl+bl, xr = h@Wr+br ----------------
__global__ void k_gemm(const float* __restrict__ Wl, const float* __restrict__ blv,
                       const float* __restrict__ Wr, const float* __restrict__ brv,
                       int n) {
    extern __shared__ float sm[];
    float* sWl = sm;              // 16384 floats
    float* sWr = sm + 16384;      // 16384
    float* sA  = sm + 32768;      // 16384 (128 rows x 128)
    int tid = threadIdx.x;
    for (int i = tid; i < 4096; i += 512) {
        ((float4*)sWl)[i] = ((const float4*)Wl)[i];
        ((float4*)sWr)[i] = ((const float4*)Wr)[i];
    }
    int row0 = blockIdx.x * 128;
    for (int i = tid; i < 4096; i += 512) {
        int r = i >> 5, c4 = i & 31;
        int gr = row0 + r;
        float4 v = (gr < n) ? ((const float4*)g_h)[gr * 32 + c4]
                            : make_float4(0.f, 0.f, 0.f, 0.f);
        ((float4*)sA)[i] = v;
    }
    __syncthreads();
    int warp = tid >> 5, lane = tid & 31;
    float4 bL = ((const float4*)blv)[lane];
    float4 bR = ((const float4*)brv)[lane];
    unsigned long long aL[8][2], aR[8][2];
    #pragma unroll
    for (int r = 0; r < 8; r++) {
        aL[r][0] = pack2f(bL.x, bL.y); aL[r][1] = pack2f(bL.z, bL.w);
        aR[r][0] = pack2f(bR.x, bR.y); aR[r][1] = pack2f(bR.z, bR.w);
    }
    const ulonglong2* sWl2 = (const ulonglong2*)sWl;
    const ulonglong2* sWr2 = (const ulonglong2*)sWr;
    const float* sArow = sA + warp * 8 * 128;
    #pragma unroll 4
    for (int k = 0; k < 128; k++) {
        ulonglong2 wl = sWl2[k * 32 + lane];
        ulonglong2 wr = sWr2[k * 32 + lane];
        #pragma unroll
        for (int r = 0; r < 8; r++) {
            unsigned long long ap = pack2(sArow[r * 128 + k]);
            aL[r][0] = fma2(ap, wl.x, aL[r][0]);
            aL[r][1] = fma2(ap, wl.y, aL[r][1]);
            aR[r][0] = fma2(ap, wr.x, aR[r][0]);
            aR[r][1] = fma2(ap, wr.y, aR[r][1]);
        }
    }
    #pragma unroll
    for (int r = 0; r < 8; r++) {
        int gr = row0 + warp * 8 + r;
        if (gr < n) {
            float2 l0 = unpack2(aL[r][0]), l1 = unpack2(aL[r][1]);
            float2 r0 = unpack2(aR[r][0]), r1 = unpack2(aR[r][1]);
            ((float4*)g_xl)[gr * 32 + lane] = make_float4(l0.x, l0.y, l1.x, l1.y);
            ((float4*)g_xr)[gr * 32 + lane] = make_float4(r0.x, r0.y, r1.x, r1.y);
        }
    }
}

// ---- fused: edge scores + online softmax + aggregation + FiLM + LN + GELU + residual ----
// one warp per node; lane owns channels 4l..4l+3 (head = lane>>3)
__global__ void k_node(const float* __restrict__ We, const float* __restrict__ att,
                       const float* __restrict__ cb, const float* __restrict__ lng,
                       const float* __restrict__ lnb, int n) {
    int tid = threadIdx.x;
    int warp = tid >> 5, lane = tid & 31;
    int i = blockIdx.x * 8 + warp;
    if (i >= n) return;

    // per-lane constants
    float4 we0 = ((const float4*)We)[lane];
    float4 we1 = ((const float4*)We)[32 + lane];
    float4 we2 = ((const float4*)We)[64 + lane];
    float4 we3 = ((const float4*)We)[96 + lane];
    float4 at  = ((const float4*)att)[lane];
    float4 xr  = ((const float4*)g_xr)[i * 32 + lane];

    int beg = g_off[i], end = g_off[i + 1];
    float mx = -1e30f;
    float sme = 0.f;
    float4 acc = make_float4(0.f, 0.f, 0.f, 0.f);

    // software-pipelined edge loop
    float4 xln, ean;
    if (beg < end) {
        int s0 = g_csrc[beg];
        ean = g_ea[beg];
        xln = ((const float4*)g_xl)[s0 * 32 + lane];
    }
    for (int j = beg; j < end; j++) {
        float4 xlv = xln, eav = ean;
        int jn = j + 1;
        if (jn < end) {
            int s1 = g_csrc[jn];
            ean = g_ea[jn];
            xln = ((const float4*)g_xl)[s1 * 32 + lane];
        }
        float m0 = xlv.x + xr.x + eav.x * we0.x + eav.y * we1.x + eav.z * we2.x + eav.w * we3.x;
        float m1 = xlv.y + xr.y + eav.x * we0.y + eav.y * we1.y + eav.z * we2.y + eav.w * we3.y;
        float m2 = xlv.z + xr.z + eav.x * we0.z + eav.y * we1.z + eav.z * we2.z + eav.w * we3.z;
        float m3 = xlv.w + xr.w + eav.x * we0.w + eav.y * we1.w + eav.z * we2.w + eav.w * we3.w;
        m0 = (m0 > 0.f) ? m0 : 0.2f * m0;
        m1 = (m1 > 0.f) ? m1 : 0.2f * m1;
        m2 = (m2 > 0.f) ? m2 : 0.2f * m2;
        m3 = (m3 > 0.f) ? m3 : 0.2f * m3;
        float p = m0 * at.x + m1 * at.y + m2 * at.z + m3 * at.w;
        // reduce within 8-lane head group
        p += __shfl_xor_sync(0xFFFFFFFFu, p, 1);
        p += __shfl_xor_sync(0xFFFFFFFFu, p, 2);
        p += __shfl_xor_sync(0xFFFFFFFFu, p, 4);
        // online softmax update
        float nm = fmaxf(mx, p);
        float scale = __expf(mx - nm);
        float w = __expf(p - nm);
        sme = sme * scale + w;
        acc.x = acc.x * scale + w * xlv.x;
        acc.y = acc.y * scale + w * xlv.y;
        acc.z = acc.z * scale + w * xlv.z;
        acc.w = acc.w * scale + w * xlv.w;
        mx = nm;
    }

    float inv = 1.0f / (sme + 1e-16f);
    float4 cb4 = ((const float4*)cb)[lane];
    float4 ga  = ((const float4*)g_gamma)[i * 32 + lane];
    float4 be  = ((const float4*)g_beta)[i * 32 + lane];
    float y0 = ga.x * (acc.x * inv + cb4.x) + be.x;
    float y1 = ga.y * (acc.y * inv + cb4.y) + be.y;
    float y2 = ga.z * (acc.z * inv + cb4.z) + be.z;
    float y3 = ga.w * (acc.w * inv + cb4.w) + be.w;
    float s1 = y0 + y1 + y2 + y3;
    float s2 = y0*y0 + y1*y1 + y2*y2 + y3*y3;
    #pragma unroll
    for (int o = 16; o > 0; o >>= 1) {
        s1 += __shfl_xor_sync(0xFFFFFFFFu, s1, o);
        s2 += __shfl_xor_sync(0xFFFFFFFFu, s2, o);
    }
    float mean = s1 * (1.0f / 128.0f);
    float var  = s2 * (1.0f / 128.0f) - mean * mean;
    float ivs  = rsqrtf(var + 1e-5f);
    float4 g4 = ((const float4*)lng)[lane];
    float4 b4 = ((const float4*)lnb)[lane];
    float4 ho = ((const float4*)g_h)[i * 32 + lane];
    float4 out;
    out.x = gelu_f((y0 - mean) * ivs * g4.x + b4.x) + ho.x;
    out.y = gelu_f((y1 - mean) * ivs * g4.y + b4.y) + ho.y;
    out.z = gelu_f((y2 - mean) * ivs * g4.z + b4.z) + ho.z;
    out.w = gelu_f((y3 - mean) * ivs * g4.w + b4.w) + ho.w;
    ((float4*)g_h)[i * 32 + lane] = out;
}

// ---------------- decoder + mask + output ----------------
__global__ void k_dec(const float* __restrict__ W1, const float* __restrict__ b1,
                      const float* __restrict__ W2, const float* __restrict__ b2,
                      const float* __restrict__ x, const void* __restrict__ mask,
                      float* __restrict__ out, int n, int out_size) {
    __shared__ float sW1[8192];
    __shared__ float sW2[128];
    __shared__ float sb1v[64];
    __shared__ float sb2v[2];
    __shared__ float sH[8][128];
    int tid = threadIdx.x;
    for (int i = tid; i < 8192; i += 256) sW1[i] = W1[i];
    if (tid < 128) sW2[tid] = W2[tid];
    if (tid < 64) sb1v[tid] = b1[tid];
    if (tid < 2) sb2v[tid] = b2[tid];
    __syncthreads();
    int warp = tid >> 5, lane = tid & 31;
    int mode = g_maskmode;
    for (int i = blockIdx.x * 8 + warp; i < n; i += gridDim.x * 8) {
        #pragma unroll
        for (int h = 0; h < 4; h++) sH[warp][h * 32 + lane] = g_h[i * 128 + h * 32 + lane];
        __syncwarp();
        float a0 = sb1v[lane], a1 = sb1v[lane + 32];
        for (int k = 0; k < 128; k++) {
            float hv = sH[warp][k];
            a0 += hv * sW1[k * 64 + lane];
            a1 += hv * sW1[k * 64 + lane + 32];
        }
        float t0 = gelu_f(a0), t1 = gelu_f(a1);
        float d0 = t0 * sW2[lane * 2]     + t1 * sW2[(lane + 32) * 2];
        float d1 = t0 * sW2[lane * 2 + 1] + t1 * sW2[(lane + 32) * 2 + 1];
        #pragma unroll
        for (int o = 16; o > 0; o >>= 1) {
            d0 += __shfl_xor_sync(0xFFFFFFFFu, d0, o);
            d1 += __shfl_xor_sync(0xFFFFFFFFu, d1, o);
        }
        if (lane == 0) {
            d0 += sb2v[0]; d1 += sb2v[1];
            int fixed;
            if (mode == 0)      fixed = ((const int*)mask)[i] != 0;
            else if (mode == 1) fixed = ((const float*)mask)[i] != 0.f;
            else                fixed = ((const unsigned char*)mask)[i] != 0;
            if (fixed) { d0 = 0.f; d1 = 0.f; }
            out[i * 2]     = x[i * 6]     + d0;
            out[i * 2 + 1] = x[i * 6 + 1] + d1;
            if (out_size >= 4 * n) {
                out[2 * n + i * 2]     = d0;
                out[2 * n + i * 2 + 1] = d1;
            }
        }
        __syncwarp();
    }
}

// ---------------- launch ----------------
extern "C" void kernel_launch(void* const* d_in, const int* in_sizes, int n_in,
                              void* d_out, int out_size) {
    const float* x    = (const float*)d_in[0];
    const int*   ei   = (const int*)d_in[1];
    const float* ea   = (const float*)d_in[2];
    const float* tmp  = (const float*)d_in[3];
    const void*  mask = d_in[4];
    const float* encW = (const float*)d_in[5];
    const float* encB = (const float*)d_in[6];
    const float* encG = (const float*)d_in[7];
    const float* encBe= (const float*)d_in[8];
    const float* fW1  = (const float*)d_in[9];
    const float* fb1  = (const float*)d_in[10];
    const float* fW2  = (const float*)d_in[11];
    const float* fb2  = (const float*)d_in[12];
    const float* Wl   = (const float*)d_in[13];
    const float* bl   = (const float*)d_in[14];
    const float* Wr   = (const float*)d_in[15];
    const float* br   = (const float*)d_in[16];
    const float* We   = (const float*)d_in[17];
    const float* att  = (const float*)d_in[18];
    const float* cb   = (const float*)d_in[19];
    const float* lng  = (const float*)d_in[20];
    const float* lnb  = (const float*)d_in[21];
    const float* dW1  = (const float*)d_in[22];
    const float* db1  = (const float*)d_in[23];
    const float* dW2  = (const float*)d_in[24];
    const float* db2  = (const float*)d_in[25];
    float* out = (float*)d_out;

    int n = in_sizes[0] / 6;
    int e = in_sizes[2] / 4;

    cudaFuncSetAttribute(k_prep, cudaFuncAttributeMaxDynamicSharedMemorySize, 73728);
    cudaFuncSetAttribute(k_gemm, cudaFuncAttributeMaxDynamicSharedMemorySize, 196608);

    // CSR build + mask detection
    k_zero<<<(n + 255) / 256, 256>>>(n);
    k_maskdetect<<<32, 256>>>((const int*)mask, n);
    k_maskresolve<<<1, 1>>>();
    k_count<<<(e + 255) / 256, 256>>>(ei, e);
    k_scan<<<1, 1024>>>(n);
    k_zero<<<(n + 255) / 256, 256>>>(n);
    k_scatter<<<(e + 255) / 256, 256>>>(ei, (const float4*)ea, e);

    // encoder + FiLM
    k_prep<<<1536, 256, 72192>>>(x, tmp, encW, encB, encG, encBe,
                                 fW1, fb1, fW2, fb2, n);

    // 4 GATv2 layers
    for (int l = 0; l < 4; l++) {
        k_gemm<<<(n + 127) / 128, 512, 196608>>>(Wl + l * 16384, bl + l * 128,
                                                 Wr + l * 16384, br + l * 128, n);
        k_node<<<(n + 7) / 8, 256>>>(We + l * 512, att + l * 128,
                                     cb + l * 128, lng + l * 128, lnb + l * 128, n);
    }

    // decoder + output
    k_dec<<<1536, 256>>>(dW1, db1, dW2, db2, x, mask, out, n, out_size);
}

// round 3
// speedup vs baseline: 1.9161x; 1.0436x over previous
#include <cuda_runtime.h>
#include <cuda_fp16.h>
#include <math.h>

#define HID 128
#define NMAX 50048
#define EMAX 1600000

// ---------------- device scratch ----------------
__device__ float   g_h[NMAX * HID];
__device__ __half2 g_xlh[NMAX * 64];      // xl in fp16, row = 128 halfs = 64 half2
__device__ float   g_xr[NMAX * HID];
__device__ float   g_gamma[NMAX * HID];
__device__ float   g_beta[NMAX * HID];
__device__ float4  g_ea[EMAX];
__device__ int     g_off[NMAX + 1];
__device__ int     g_cnt[NMAX];
__device__ int     g_csrc[EMAX];
__device__ int     g_viol[2];
__device__ int     g_maskmode;

__device__ __forceinline__ float gelu_f(float x) {
    return 0.5f * x * (1.0f + erff(x * 0.7071067811865476f));
}

// packed fp32x2 helpers (Blackwell)
__device__ __forceinline__ unsigned long long fma2(unsigned long long a,
                                                   unsigned long long b,
                                                   unsigned long long c) {
    unsigned long long d;
    asm("fma.rn.f32x2 %0, %1, %2, %3;" : "=l"(d) : "l"(a), "l"(b), "l"(c));
    return d;
}
__device__ __forceinline__ unsigned long long pack2(float x) {
    unsigned long long d;
    asm("mov.b64 %0, {%1, %1};" : "=l"(d) : "f"(x));
    return d;
}
__device__ __forceinline__ unsigned long long pack2f(float a, float b) {
    unsigned long long d;
    asm("mov.b64 %0, {%1, %2};" : "=l"(d) : "f"(a), "f"(b));
    return d;
}
__device__ __forceinline__ float2 unpack2(unsigned long long v) {
    float2 r;
    asm("mov.b64 {%0, %1}, %2;" : "=f"(r.x), "=f"(r.y) : "l"(v));
    return r;
}

// ---------------- CSR build ----------------
__global__ void k_init(int n) {
    int i = blockIdx.x * blockDim.x + threadIdx.x;
    if (i < n) g_cnt[i] = 0;
    if (i < 2) g_viol[i] = 0;
}

// count incoming edges per dst + detect mask serialization
__global__ void k_count(const int* ei, const int* m, int e, int n) {
    int i = blockIdx.x * blockDim.x + threadIdx.x;
    if (i < e) atomicAdd(&g_cnt[ei[e + i]], 1);
    // mask dtype detection on first few thousand words (deterministic)
    int words = n >> 2;
    int lim = words < 8192 ? words : 8192;
    if (i < lim) {
        int v = m[i];
        if (v != 0 && v != 1) atomicOr(&g_viol[0], 1);
        if (v != 0 && v != 0x3F800000) atomicOr(&g_viol[1], 1);
    }
}

// single-block hierarchical exclusive scan; writes g_off and scatter cursors g_cnt
__global__ void k_scan(int n) {
    __shared__ int warpsum[32];
    int t = threadIdx.x;
    int per = (n + 1023) >> 10;
    int i0 = t * per;
    int i1 = i0 + per; if (i1 > n) i1 = n; if (i0 > n) i0 = n;
    int local = 0;
    for (int i = i0; i < i1; i++) local += g_cnt[i];
    int lane = t & 31, warp = t >> 5;
    int v = local;
    #pragma unroll
    for (int o = 1; o < 32; o <<= 1) {
        int u = __shfl_up_sync(0xFFFFFFFFu, v, o);
        if (lane >= o) v += u;
    }
    if (lane == 31) warpsum[warp] = v;
    __syncthreads();
    if (warp == 0) {
        int w = warpsum[lane];
        #pragma unroll
        for (int o = 1; o < 32; o <<= 1) {
            int u = __shfl_up_sync(0xFFFFFFFFu, w, o);
            if (lane >= o) w += u;
        }
        warpsum[lane] = w;
    }
    __syncthreads();
    int excl = v - local + (warp ? warpsum[warp - 1] : 0);
    int run = excl;
    for (int i = i0; i < i1; i++) {
        int c = g_cnt[i];
        g_off[i] = run;
        g_cnt[i] = run;   // cursor for scatter
        run += c;
    }
    if (t == 1023) g_off[n] = run;
    if (t == 0) g_maskmode = (g_viol[0] == 0) ? 0 : ((g_viol[1] == 0) ? 1 : 2);
}

__global__ void k_scatter(const int* ei, const float4* __restrict__ ea, int e) {
    int i = blockIdx.x * blockDim.x + threadIdx.x;
    if (i >= e) return;
    int s = ei[i], d = ei[e + i];
    int pos = atomicAdd(&g_cnt[d], 1);
    g_csrc[pos] = s;
    g_ea[pos] = ea[i];
}

// ---------------- encoder + FiLM (one warp per node) ----------------
__global__ void k_prep(const float* __restrict__ x, const float* __restrict__ tmp,
                       const float* __restrict__ encW, const float* __restrict__ encB,
                       const float* __restrict__ encG, const float* __restrict__ encBe,
                       const float* __restrict__ fW1, const float* __restrict__ fb1,
                       const float* __restrict__ fW2, const float* __restrict__ fb2,
                       int n) {
    extern __shared__ float sm[];
    float* sEncW = sm;            // 768
    float* sW1   = sm + 768;      // 64
    float* sB1   = sm + 832;      // 64
    float* sB2   = sm + 896;      // 256
    float* sW2   = sm + 1152;     // 16384
    float* sT1   = sm + 17536;    // 512
    int tid = threadIdx.x;
    for (int i = tid; i < 768; i += blockDim.x) sEncW[i] = encW[i];
    for (int i = tid; i < 64; i += blockDim.x) { sW1[i] = fW1[i]; sB1[i] = fb1[i]; }
    for (int i = tid; i < 256; i += blockDim.x) sB2[i] = fb2[i];
    for (int i = tid; i < 4096; i += blockDim.x)
        ((float4*)sW2)[i] = ((const float4*)fW2)[i];
    __syncthreads();
    int warp = tid >> 5, lane = tid & 31;
    for (int i = blockIdx.x * 8 + warp; i < n; i += gridDim.x * 8) {
        float xv[6];
        #pragma unroll
        for (int j = 0; j < 6; j++) xv[j] = x[i * 6 + j];
        float y[4];
        #pragma unroll
        for (int h = 0; h < 4; h++) {
            int k = h * 32 + lane;
            float a = encB[k];
            #pragma unroll
            for (int j = 0; j < 6; j++) a += xv[j] * sEncW[j * 128 + k];
            y[h] = a;
        }
        float s1 = y[0] + y[1] + y[2] + y[3];
        float s2 = y[0]*y[0] + y[1]*y[1] + y[2]*y[2] + y[3]*y[3];
        #pragma unroll
        for (int o = 16; o > 0; o >>= 1) {
            s1 += __shfl_xor_sync(0xFFFFFFFFu, s1, o);
            s2 += __shfl_xor_sync(0xFFFFFFFFu, s2, o);
        }
        float mean = s1 * (1.0f / 128.0f);
        float var  = s2 * (1.0f / 128.0f) - mean * mean;
        float inv  = rsqrtf(var + 1e-5f);
        #pragma unroll
        for (int h = 0; h < 4; h++) {
            int k = h * 32 + lane;
            float v = (y[h] - mean) * inv * encG[k] + encBe[k];
            g_h[i * 128 + k] = gelu_f(v);
        }
        float tm = tmp[i];
        #pragma unroll
        for (int c = 0; c < 2; c++) {
            int j = lane + 32 * c;
            sT1[warp * 64 + j] = gelu_f(tm * sW1[j] + sB1[j]);
        }
        __syncwarp();
        float f[8];
        #pragma unroll
        for (int c = 0; c < 8; c++) f[c] = sB2[lane + 32 * c];
        for (int j = 0; j < 64; j++) {
            float t = sT1[warp * 64 + j];
            #pragma unroll
            for (int c = 0; c < 8; c++) f[c] += t * sW2[j * 256 + lane + 32 * c];
        }
        #pragma unroll
        for (int c = 0; c < 4; c++) {
            g_gamma[i * 128 + lane + 32 * c] = f[c];
            g_beta[i * 128 + lane + 32 * c]  = f[c + 4];
        }
        __syncwarp();
    }
}

// ---------------- dual GEMM (packed f32x2): xl(fp16) = h@Wl+bl, xr = h@Wr+br ----------------
__global__ void k_gemm(const float* __restrict__ Wl, const float* __restrict__ blv,
                       const float* __restrict__ Wr, const float* __restrict__ brv,
                       int n) {
    extern __shared__ float sm[];
    float* sWl = sm;              // 16384
    float* sWr = sm + 16384;      // 16384
    float* sA  = sm + 32768;      // 16384 (128 rows x 128)
    int tid = threadIdx.x;
    for (int i = tid; i < 4096; i += 512) {
        ((float4*)sWl)[i] = ((const float4*)Wl)[i];
        ((float4*)sWr)[i] = ((const float4*)Wr)[i];
    }
    int row0 = blockIdx.x * 128;
    for (int i = tid; i < 4096; i += 512) {
        int r = i >> 5, c4 = i & 31;
        int gr = row0 + r;
        float4 v = (gr < n) ? ((const float4*)g_h)[gr * 32 + c4]
                            : make_float4(0.f, 0.f, 0.f, 0.f);
        ((float4*)sA)[i] = v;
    }
    __syncthreads();
    int warp = tid >> 5, lane = tid & 31;
    float4 bL = ((const float4*)blv)[lane];
    float4 bR = ((const float4*)brv)[lane];
    unsigned long long aL[8][2], aR[8][2];
    #pragma unroll
    for (int r = 0; r < 8; r++) {
        aL[r][0] = pack2f(bL.x, bL.y); aL[r][1] = pack2f(bL.z, bL.w);
        aR[r][0] = pack2f(bR.x, bR.y); aR[r][1] = pack2f(bR.z, bR.w);
    }
    const ulonglong2* sWl2 = (const ulonglong2*)sWl;
    const ulonglong2* sWr2 = (const ulonglong2*)sWr;
    const float* sArow = sA + warp * 8 * 128;
    #pragma unroll 4
    for (int k = 0; k < 128; k++) {
        ulonglong2 wl = sWl2[k * 32 + lane];
        ulonglong2 wr = sWr2[k * 32 + lane];
        #pragma unroll
        for (int r = 0; r < 8; r++) {
            unsigned long long ap = pack2(sArow[r * 128 + k]);
            aL[r][0] = fma2(ap, wl.x, aL[r][0]);
            aL[r][1] = fma2(ap, wl.y, aL[r][1]);
            aR[r][0] = fma2(ap, wr.x, aR[r][0]);
            aR[r][1] = fma2(ap, wr.y, aR[r][1]);
        }
    }
    #pragma unroll
    for (int r = 0; r < 8; r++) {
        int gr = row0 + warp * 8 + r;
        if (gr < n) {
            float2 l0 = unpack2(aL[r][0]), l1 = unpack2(aL[r][1]);
            float2 r0 = unpack2(aR[r][0]), r1 = unpack2(aR[r][1]);
            // xl stored fp16 (gather payload)
            __half2 h0 = __floats2half2_rn(l0.x, l0.y);
            __half2 h1 = __floats2half2_rn(l1.x, l1.y);
            uint2 packed;
            packed.x = *(unsigned int*)&h0;
            packed.y = *(unsigned int*)&h1;
            ((uint2*)g_xlh)[gr * 32 + lane] = packed;
            ((float4*)g_xr)[gr * 32 + lane] = make_float4(r0.x, r0.y, r1.x, r1.y);
        }
    }
}

// ---- fused: edge scores + online softmax + aggregation + FiLM + LN + GELU + residual ----
// one warp per node; lane owns channels 4l..4l+3 (head = lane>>3)
__global__ void k_node(const float* __restrict__ We, const float* __restrict__ att,
                       const float* __restrict__ cb, const float* __restrict__ lng,
                       const float* __restrict__ lnb, int n) {
    int tid = threadIdx.x;
    int warp = tid >> 5, lane = tid & 31;
    int i = blockIdx.x * 8 + warp;
    if (i >= n) return;

    float4 we0 = ((const float4*)We)[lane];
    float4 we1 = ((const float4*)We)[32 + lane];
    float4 we2 = ((const float4*)We)[64 + lane];
    float4 we3 = ((const float4*)We)[96 + lane];
    float4 at  = ((const float4*)att)[lane];
    float4 xr  = ((const float4*)g_xr)[i * 32 + lane];

    int beg = g_off[i], end = g_off[i + 1];
    float mx = -1e30f;
    float sme = 0.f;
    float4 acc = make_float4(0.f, 0.f, 0.f, 0.f);

    const uint2* xlh = (const uint2*)g_xlh;

    uint2 xraw; float4 ean;
    if (beg < end) {
        int s0 = g_csrc[beg];
        ean = g_ea[beg];
        xraw = xlh[s0 * 32 + lane];
    }
    for (int j = beg; j < end; j++) {
        uint2 cr = xraw; float4 eav = ean;
        int jn = j + 1;
        if (jn < end) {
            int s1 = g_csrc[jn];
            ean = g_ea[jn];
            xraw = xlh[s1 * 32 + lane];
        }
        __half2 h0 = *(__half2*)&cr.x;
        __half2 h1 = *(__half2*)&cr.y;
        float2 lo = __half22float2(h0);
        float2 hi = __half22float2(h1);
        float4 xlv = make_float4(lo.x, lo.y, hi.x, hi.y);
        float m0 = xlv.x + xr.x + eav.x * we0.x + eav.y * we1.x + eav.z * we2.x + eav.w * we3.x;
        float m1 = xlv.y + xr.y + eav.x * we0.y + eav.y * we1.y + eav.z * we2.y + eav.w * we3.y;
        float m2 = xlv.z + xr.z + eav.x * we0.z + eav.y * we1.z + eav.z * we2.z + eav.w * we3.z;
        float m3 = xlv.w + xr.w + eav.x * we0.w + eav.y * we1.w + eav.z * we2.w + eav.w * we3.w;
        m0 = (m0 > 0.f) ? m0 : 0.2f * m0;
        m1 = (m1 > 0.f) ? m1 : 0.2f * m1;
        m2 = (m2 > 0.f) ? m2 : 0.2f * m2;
        m3 = (m3 > 0.f) ? m3 : 0.2f * m3;
        float p = m0 * at.x + m1 * at.y + m2 * at.z + m3 * at.w;
        p += __shfl_xor_sync(0xFFFFFFFFu, p, 1);
        p += __shfl_xor_sync(0xFFFFFFFFu, p, 2);
        p += __shfl_xor_sync(0xFFFFFFFFu, p, 4);
        float nm = fmaxf(mx, p);
        float scale = __expf(mx - nm);
        float w = __expf(p - nm);
        sme = sme * scale + w;
        acc.x = acc.x * scale + w * xlv.x;
        acc.y = acc.y * scale + w * xlv.y;
        acc.z = acc.z * scale + w * xlv.z;
        acc.w = acc.w * scale + w * xlv.w;
        mx = nm;
    }

    float inv = 1.0f / (sme + 1e-16f);
    float4 cb4 = ((const float4*)cb)[lane];
    float4 ga  = ((const float4*)g_gamma)[i * 32 + lane];
    float4 be  = ((const float4*)g_beta)[i * 32 + lane];
    float y0 = ga.x * (acc.x * inv + cb4.x) + be.x;
    float y1 = ga.y * (acc.y * inv + cb4.y) + be.y;
    float y2 = ga.z * (acc.z * inv + cb4.z) + be.z;
    float y3 = ga.w * (acc.w * inv + cb4.w) + be.w;
    float s1 = y0 + y1 + y2 + y3;
    float s2 = y0*y0 + y1*y1 + y2*y2 + y3*y3;
    #pragma unroll
    for (int o = 16; o > 0; o >>= 1) {
        s1 += __shfl_xor_sync(0xFFFFFFFFu, s1, o);
        s2 += __shfl_xor_sync(0xFFFFFFFFu, s2, o);
    }
    float mean = s1 * (1.0f / 128.0f);
    float var  = s2 * (1.0f / 128.0f) - mean * mean;
    float ivs  = rsqrtf(var + 1e-5f);
    float4 g4 = ((const float4*)lng)[lane];
    float4 b4 = ((const float4*)lnb)[lane];
    float4 ho = ((const float4*)g_h)[i * 32 + lane];
    float4 out;
    out.x = gelu_f((y0 - mean) * ivs * g4.x + b4.x) + ho.x;
    out.y = gelu_f((y1 - mean) * ivs * g4.y + b4.y) + ho.y;
    out.z = gelu_f((y2 - mean) * ivs * g4.z + b4.z) + ho.z;
    out.w = gelu_f((y3 - mean) * ivs * g4.w + b4.w) + ho.w;
    ((float4*)g_h)[i * 32 + lane] = out;
}

// ---------------- decoder + mask + output ----------------
__global__ void k_dec(const float* __restrict__ W1, const float* __restrict__ b1,
                      const float* __restrict__ W2, const float* __restrict__ b2,
                      const float* __restrict__ x, const void* __restrict__ mask,
                      float* __restrict__ out, int n, int out_size) {
    __shared__ float sW1[8192];
    __shared__ float sW2[128];
    __shared__ float sb1v[64];
    __shared__ float sb2v[2];
    __shared__ float sH[8][128];
    int tid = threadIdx.x;
    for (int i = tid; i < 8192; i += 256) sW1[i] = W1[i];
    if (tid < 128) sW2[tid] = W2[tid];
    if (tid < 64) sb1v[tid] = b1[tid];
    if (tid < 2) sb2v[tid] = b2[tid];
    __syncthreads();
    int warp = tid >> 5, lane = tid & 31;
    int mode = g_maskmode;
    for (int i = blockIdx.x * 8 + warp; i < n; i += gridDim.x * 8) {
        #pragma unroll
        for (int h = 0; h < 4; h++) sH[warp][h * 32 + lane] = g_h[i * 128 + h * 32 + lane];
        __syncwarp();
        float a0 = sb1v[lane], a1 = sb1v[lane + 32];
        for (int k = 0; k < 128; k++) {
            float hv = sH[warp][k];
            a0 += hv * sW1[k * 64 + lane];
            a1 += hv * sW1[k * 64 + lane + 32];
        }
        float t0 = gelu_f(a0), t1 = gelu_f(a1);
        float d0 = t0 * sW2[lane * 2]     + t1 * sW2[(lane + 32) * 2];
        float d1 = t0 * sW2[lane * 2 + 1] + t1 * sW2[(lane + 32) * 2 + 1];
        #pragma unroll
        for (int o = 16; o > 0; o >>= 1) {
            d0 += __shfl_xor_sync(0xFFFFFFFFu, d0, o);
            d1 += __shfl_xor_sync(0xFFFFFFFFu, d1, o);
        }
        if (lane == 0) {
            d0 += sb2v[0]; d1 += sb2v[1];
            int fixed;
            if (mode == 0)      fixed = ((const int*)mask)[i] != 0;
            else if (mode == 1) fixed = ((const float*)mask)[i] != 0.f;
            else                fixed = ((const unsigned char*)mask)[i] != 0;
            if (fixed) { d0 = 0.f; d1 = 0.f; }
            out[i * 2]     = x[i * 6]     + d0;
            out[i * 2 + 1] = x[i * 6 + 1] + d1;
            if (out_size >= 4 * n) {
                out[2 * n + i * 2]     = d0;
                out[2 * n + i * 2 + 1] = d1;
            }
        }
        __syncwarp();
    }
}

// ---------------- launch ----------------
extern "C" void kernel_launch(void* const* d_in, const int* in_sizes, int n_in,
                              void* d_out, int out_size) {
    const float* x    = (const float*)d_in[0];
    const int*   ei   = (const int*)d_in[1];
    const float* ea   = (const float*)d_in[2];
    const float* tmp  = (const float*)d_in[3];
    const void*  mask = d_in[4];
    const float* encW = (const float*)d_in[5];
    const float* encB = (const float*)d_in[6];
    const float* encG = (const float*)d_in[7];
    const float* encBe= (const float*)d_in[8];
    const float* fW1  = (const float*)d_in[9];
    const float* fb1  = (const float*)d_in[10];
    const float* fW2  = (const float*)d_in[11];
    const float* fb2  = (const float*)d_in[12];
    const float* Wl   = (const float*)d_in[13];
    const float* bl   = (const float*)d_in[14];
    const float* Wr   = (const float*)d_in[15];
    const float* br   = (const float*)d_in[16];
    const float* We   = (const float*)d_in[17];
    const float* att  = (const float*)d_in[18];
    const float* cb   = (const float*)d_in[19];
    const float* lng  = (const float*)d_in[20];
    const float* lnb  = (const float*)d_in[21];
    const float* dW1  = (const float*)d_in[22];
    const float* db1  = (const float*)d_in[23];
    const float* dW2  = (const float*)d_in[24];
    const float* db2  = (const float*)d_in[25];
    float* out = (float*)d_out;

    int n = in_sizes[0] / 6;
    int e = in_sizes[2] / 4;

    cudaFuncSetAttribute(k_prep, cudaFuncAttributeMaxDynamicSharedMemorySize, 73728);
    cudaFuncSetAttribute(k_gemm, cudaFuncAttributeMaxDynamicSharedMemorySize, 196608);

    // CSR build (4 launches)
    k_init<<<(n + 255) / 256, 256>>>(n);
    k_count<<<(e + 255) / 256, 256>>>(ei, (const int*)mask, e, n);
    k_scan<<<1, 1024>>>(n);
    k_scatter<<<(e + 255) / 256, 256>>>(ei, (const float4*)ea, e);

    // encoder + FiLM (launch 4)
    k_prep<<<592, 256, 72192>>>(x, tmp, encW, encB, encG, encBe,
                                fW1, fb1, fW2, fb2, n);

    // 4 GATv2 layers (launches 5..12: gemm/node alternating)
    for (int l = 0; l < 4; l++) {
        k_gemm<<<(n + 127) / 128, 512, 196608>>>(Wl + l * 16384, bl + l * 128,
                                                 Wr + l * 16384, br + l * 128, n);
        k_node<<<(n + 7) / 8, 256>>>(We + l * 512, att + l * 128,
                                     cb + l * 128, lng + l * 128, lnb + l * 128, n);
    }

    // decoder + output
    k_dec<<<1536, 256>>>(dW1, db1, dW2, db2, x, mask, out, n, out_size);
}

// round 4
// speedup vs baseline: 2.0226x; 1.0556x over previous
#include <cuda_runtime.h>
#include <cuda_fp16.h>
#include <math.h>

#define HID 128
#define NMAX 50048
#define EMAX 1600000

// ---------------- device scratch ----------------
__device__ float   g_h[NMAX * HID];
__device__ __half2 g_xlh[NMAX * 64];      // xl in fp16, row = 128 halfs = 64 half2
__device__ float   g_xr[NMAX * HID];
__device__ float   g_gamma[NMAX * HID];
__device__ float   g_beta[NMAX * HID];
__device__ float4  g_ea[EMAX];
__device__ int     g_off[NMAX + 1];
__device__ int     g_cnt[NMAX];           // zero-init at load; re-zeroed by k_dec
__device__ int     g_csrc[EMAX];
__device__ int     g_viol[2];
__device__ int     g_maskmode;

__device__ __forceinline__ float gelu_f(float x) {
    return 0.5f * x * (1.0f + erff(x * 0.7071067811865476f));
}

// packed fp32x2 helpers (Blackwell)
__device__ __forceinline__ unsigned long long fma2(unsigned long long a,
                                                   unsigned long long b,
                                                   unsigned long long c) {
    unsigned long long d;
    asm("fma.rn.f32x2 %0, %1, %2, %3;" : "=l"(d) : "l"(a), "l"(b), "l"(c));
    return d;
}
__device__ __forceinline__ unsigned long long pack2(float x) {
    unsigned long long d;
    asm("mov.b64 %0, {%1, %1};" : "=l"(d) : "f"(x));
    return d;
}
__device__ __forceinline__ unsigned long long pack2f(float a, float b) {
    unsigned long long d;
    asm("mov.b64 %0, {%1, %2};" : "=l"(d) : "f"(a), "f"(b));
    return d;
}
__device__ __forceinline__ float2 unpack2(unsigned long long v) {
    float2 r;
    asm("mov.b64 {%0, %1}, %2;" : "=f"(r.x), "=f"(r.y) : "l"(v));
    return r;
}

// ---------------- CSR build ----------------
// count incoming edges per dst + detect mask serialization
__global__ void k_count(const int* ei, const int* m, int e, int n) {
    int i = blockIdx.x * blockDim.x + threadIdx.x;
    if (i < e) atomicAdd(&g_cnt[ei[e + i]], 1);
    int words = n >> 2;
    int lim = words < 8192 ? words : 8192;
    if (i < lim) {
        int v = m[i];
        if (v != 0 && v != 1) atomicOr(&g_viol[0], 1);
        if (v != 0 && v != 0x3F800000) atomicOr(&g_viol[1], 1);
    }
}

// single-block hierarchical exclusive scan; writes g_off and scatter cursors g_cnt
__global__ void k_scan(int n) {
    __shared__ int warpsum[32];
    int t = threadIdx.x;
    int per = (n + 1023) >> 10;
    int i0 = t * per;
    int i1 = i0 + per; if (i1 > n) i1 = n; if (i0 > n) i0 = n;
    int local = 0;
    for (int i = i0; i < i1; i++) local += g_cnt[i];
    int lane = t & 31, warp = t >> 5;
    int v = local;
    #pragma unroll
    for (int o = 1; o < 32; o <<= 1) {
        int u = __shfl_up_sync(0xFFFFFFFFu, v, o);
        if (lane >= o) v += u;
    }
    if (lane == 31) warpsum[warp] = v;
    __syncthreads();
    if (warp == 0) {
        int w = warpsum[lane];
        #pragma unroll
        for (int o = 1; o < 32; o <<= 1) {
            int u = __shfl_up_sync(0xFFFFFFFFu, w, o);
            if (lane >= o) w += u;
        }
        warpsum[lane] = w;
    }
    __syncthreads();
    int excl = v - local + (warp ? warpsum[warp - 1] : 0);
    int run = excl;
    for (int i = i0; i < i1; i++) {
        int c = g_cnt[i];
        g_off[i] = run;
        g_cnt[i] = run;   // cursor for scatter
        run += c;
    }
    if (t == 1023) g_off[n] = run;
    if (t == 0) g_maskmode = (g_viol[0] == 0) ? 0 : ((g_viol[1] == 0) ? 1 : 2);
}

__global__ void k_scatter(const int* ei, const float4* __restrict__ ea, int e) {
    int i = blockIdx.x * blockDim.x + threadIdx.x;
    if (i >= e) return;
    int s = ei[i], d = ei[e + i];
    int pos = atomicAdd(&g_cnt[d], 1);
    g_csrc[pos] = s;
    g_ea[pos] = ea[i];
}

// ---------------- encoder + FiLM (one warp per node) ----------------
__global__ void k_prep(const float* __restrict__ x, const float* __restrict__ tmp,
                       const float* __restrict__ encW, const float* __restrict__ encB,
                       const float* __restrict__ encG, const float* __restrict__ encBe,
                       const float* __restrict__ fW1, const float* __restrict__ fb1,
                       const float* __restrict__ fW2, const float* __restrict__ fb2,
                       int n) {
    extern __shared__ float sm[];
    float* sEncW = sm;            // 768
    float* sW1   = sm + 768;      // 64
    float* sB1   = sm + 832;      // 64
    float* sB2   = sm + 896;      // 256
    float* sW2   = sm + 1152;     // 16384
    float* sT1   = sm + 17536;    // 512
    int tid = threadIdx.x;
    for (int i = tid; i < 768; i += blockDim.x) sEncW[i] = encW[i];
    for (int i = tid; i < 64; i += blockDim.x) { sW1[i] = fW1[i]; sB1[i] = fb1[i]; }
    for (int i = tid; i < 256; i += blockDim.x) sB2[i] = fb2[i];
    for (int i = tid; i < 4096; i += blockDim.x)
        ((float4*)sW2)[i] = ((const float4*)fW2)[i];
    __syncthreads();
    int warp = tid >> 5, lane = tid & 31;
    for (int i = blockIdx.x * 8 + warp; i < n; i += gridDim.x * 8) {
        float xv[6];
        #pragma unroll
        for (int j = 0; j < 6; j++) xv[j] = x[i * 6 + j];
        float y[4];
        #pragma unroll
        for (int h = 0; h < 4; h++) {
            int k = h * 32 + lane;
            float a = encB[k];
            #pragma unroll
            for (int j = 0; j < 6; j++) a += xv[j] * sEncW[j * 128 + k];
            y[h] = a;
        }
        float s1 = y[0] + y[1] + y[2] + y[3];
        float s2 = y[0]*y[0] + y[1]*y[1] + y[2]*y[2] + y[3]*y[3];
        #pragma unroll
        for (int o = 16; o > 0; o >>= 1) {
            s1 += __shfl_xor_sync(0xFFFFFFFFu, s1, o);
            s2 += __shfl_xor_sync(0xFFFFFFFFu, s2, o);
        }
        float mean = s1 * (1.0f / 128.0f);
        float var  = s2 * (1.0f / 128.0f) - mean * mean;
        float inv  = rsqrtf(var + 1e-5f);
        #pragma unroll
        for (int h = 0; h < 4; h++) {
            int k = h * 32 + lane;
            float v = (y[h] - mean) * inv * encG[k] + encBe[k];
            g_h[i * 128 + k] = gelu_f(v);
        }
        float tm = tmp[i];
        #pragma unroll
        for (int c = 0; c < 2; c++) {
            int j = lane + 32 * c;
            sT1[warp * 64 + j] = gelu_f(tm * sW1[j] + sB1[j]);
        }
        __syncwarp();
        float f[8];
        #pragma unroll
        for (int c = 0; c < 8; c++) f[c] = sB2[lane + 32 * c];
        for (int j = 0; j < 64; j++) {
            float t = sT1[warp * 64 + j];
            #pragma unroll
            for (int c = 0; c < 8; c++) f[c] += t * sW2[j * 256 + lane + 32 * c];
        }
        #pragma unroll
        for (int c = 0; c < 4; c++) {
            g_gamma[i * 128 + lane + 32 * c] = f[c];
            g_beta[i * 128 + lane + 32 * c]  = f[c + 4];
        }
        __syncwarp();
    }
}

// ---------------- dual GEMM (packed f32x2): xl(fp16) = h@Wl+bl, xr = h@Wr+br ----------------
__global__ void k_gemm(const float* __restrict__ Wl, const float* __restrict__ blv,
                       const float* __restrict__ Wr, const float* __restrict__ brv,
                       int n) {
    extern __shared__ float sm[];
    float* sWl = sm;              // 16384
    float* sWr = sm + 16384;      // 16384
    float* sA  = sm + 32768;      // 16384 (128 rows x 128)
    int tid = threadIdx.x;
    for (int i = tid; i < 4096; i += 512) {
        ((float4*)sWl)[i] = ((const float4*)Wl)[i];
        ((float4*)sWr)[i] = ((const float4*)Wr)[i];
    }
    int row0 = blockIdx.x * 128;
    for (int i = tid; i < 4096; i += 512) {
        int r = i >> 5, c4 = i & 31;
        int gr = row0 + r;
        float4 v = (gr < n) ? ((const float4*)g_h)[gr * 32 + c4]
                            : make_float4(0.f, 0.f, 0.f, 0.f);
        ((float4*)sA)[i] = v;
    }
    __syncthreads();
    int warp = tid >> 5, lane = tid & 31;
    float4 bL = ((const float4*)blv)[lane];
    float4 bR = ((const float4*)brv)[lane];
    unsigned long long aL[8][2], aR[8][2];
    #pragma unroll
    for (int r = 0; r < 8; r++) {
        aL[r][0] = pack2f(bL.x, bL.y); aL[r][1] = pack2f(bL.z, bL.w);
        aR[r][0] = pack2f(bR.x, bR.y); aR[r][1] = pack2f(bR.z, bR.w);
    }
    const ulonglong2* sWl2 = (const ulonglong2*)sWl;
    const ulonglong2* sWr2 = (const ulonglong2*)sWr;
    const float* sArow = sA + warp * 8 * 128;
    #pragma unroll 4
    for (int k = 0; k < 128; k++) {
        ulonglong2 wl = sWl2[k * 32 + lane];
        ulonglong2 wr = sWr2[k * 32 + lane];
        #pragma unroll
        for (int r = 0; r < 8; r++) {
            unsigned long long ap = pack2(sArow[r * 128 + k]);
            aL[r][0] = fma2(ap, wl.x, aL[r][0]);
            aL[r][1] = fma2(ap, wl.y, aL[r][1]);
            aR[r][0] = fma2(ap, wr.x, aR[r][0]);
            aR[r][1] = fma2(ap, wr.y, aR[r][1]);
        }
    }
    #pragma unroll
    for (int r = 0; r < 8; r++) {
        int gr = row0 + warp * 8 + r;
        if (gr < n) {
            float2 l0 = unpack2(aL[r][0]), l1 = unpack2(aL[r][1]);
            float2 r0 = unpack2(aR[r][0]), r1 = unpack2(aR[r][1]);
            __half2 h0 = __floats2half2_rn(l0.x, l0.y);
            __half2 h1 = __floats2half2_rn(l1.x, l1.y);
            uint2 packed;
            packed.x = *(unsigned int*)&h0;
            packed.y = *(unsigned int*)&h1;
            ((uint2*)g_xlh)[gr * 32 + lane] = packed;
            ((float4*)g_xr)[gr * 32 + lane] = make_float4(r0.x, r0.y, r1.x, r1.y);
        }
    }
}

// ---- fused: edge scores + softmax (no-max, exact ratios) + aggregation + FiLM + LN + GELU + residual ----
// one warp per node; lane owns channels 4l..4l+3 (head = lane>>3); 4 edges per iteration
__global__ void k_node(const float* __restrict__ We, const float* __restrict__ att,
                       const float* __restrict__ cb, const float* __restrict__ lng,
                       const float* __restrict__ lnb, int n) {
    int tid = threadIdx.x;
    int warp = tid >> 5, lane = tid & 31;
    int i = blockIdx.x * 8 + warp;
    if (i >= n) return;

    float4 we0 = ((const float4*)We)[lane];
    float4 we1 = ((const float4*)We)[32 + lane];
    float4 we2 = ((const float4*)We)[64 + lane];
    float4 we3 = ((const float4*)We)[96 + lane];
    float4 at  = ((const float4*)att)[lane];
    float4 xr  = ((const float4*)g_xr)[i * 32 + lane];

    int beg = g_off[i], end = g_off[i + 1];
    float sme = 0.f;
    float4 acc = make_float4(0.f, 0.f, 0.f, 0.f);
    const uint2* xlh = (const uint2*)g_xlh;

    for (int j = beg; j < end; j += 4) {
        int c = end - j;
        // batched independent loads (MLP=4)
        int s0 = g_csrc[j];
        int s1 = (c > 1) ? g_csrc[j + 1] : s0;
        int s2 = (c > 2) ? g_csrc[j + 2] : s0;
        int s3 = (c > 3) ? g_csrc[j + 3] : s0;
        float4 e0 = g_ea[j];
        float4 e1 = (c > 1) ? g_ea[j + 1] : e0;
        float4 e2 = (c > 2) ? g_ea[j + 2] : e0;
        float4 e3 = (c > 3) ? g_ea[j + 3] : e0;
        uint2 r0 = xlh[s0 * 32 + lane];
        uint2 r1 = xlh[s1 * 32 + lane];
        uint2 r2 = xlh[s2 * 32 + lane];
        uint2 r3 = xlh[s3 * 32 + lane];

        float4 x0, x1, x2, x3;
        float p0, p1, p2, p3;
        #define EDGE_SCORE(rr, ee, xx, pp)                                           \
        {                                                                            \
            float2 lo = __half22float2(*(__half2*)&rr.x);                            \
            float2 hi = __half22float2(*(__half2*)&rr.y);                            \
            xx = make_float4(lo.x, lo.y, hi.x, hi.y);                                \
            float m0 = xx.x + xr.x + ee.x*we0.x + ee.y*we1.x + ee.z*we2.x + ee.w*we3.x; \
            float m1 = xx.y + xr.y + ee.x*we0.y + ee.y*we1.y + ee.z*we2.y + ee.w*we3.y; \
            float m2 = xx.z + xr.z + ee.x*we0.z + ee.y*we1.z + ee.z*we2.z + ee.w*we3.z; \
            float m3 = xx.w + xr.w + ee.x*we0.w + ee.y*we1.w + ee.z*we2.w + ee.w*we3.w; \
            m0 = (m0 > 0.f) ? m0 : 0.2f * m0;                                        \
            m1 = (m1 > 0.f) ? m1 : 0.2f * m1;                                        \
            m2 = (m2 > 0.f) ? m2 : 0.2f * m2;                                        \
            m3 = (m3 > 0.f) ? m3 : 0.2f * m3;                                        \
            pp = m0*at.x + m1*at.y + m2*at.z + m3*at.w;                              \
        }
        EDGE_SCORE(r0, e0, x0, p0)
        EDGE_SCORE(r1, e1, x1, p1)
        EDGE_SCORE(r2, e2, x2, p2)
        EDGE_SCORE(r3, e3, x3, p3)
        #undef EDGE_SCORE

        // independent head-group reductions (pipeline across 4 edges)
        #pragma unroll
        for (int o = 1; o < 8; o <<= 1) {
            p0 += __shfl_xor_sync(0xFFFFFFFFu, p0, o);
            p1 += __shfl_xor_sync(0xFFFFFFFFu, p1, o);
            p2 += __shfl_xor_sync(0xFFFFFFFFu, p2, o);
            p3 += __shfl_xor_sync(0xFFFFFFFFu, p3, o);
        }
        float w0 = __expf(p0);
        float w1 = (c > 1) ? __expf(p1) : 0.f;
        float w2 = (c > 2) ? __expf(p2) : 0.f;
        float w3 = (c > 3) ? __expf(p3) : 0.f;
        sme += (w0 + w1) + (w2 + w3);
        acc.x += w0*x0.x + w1*x1.x + w2*x2.x + w3*x3.x;
        acc.y += w0*x0.y + w1*x1.y + w2*x2.y + w3*x3.y;
        acc.z += w0*x0.z + w1*x1.z + w2*x2.z + w3*x3.z;
        acc.w += w0*x0.w + w1*x1.w + w2*x2.w + w3*x3.w;
    }

    float inv = 1.0f / (sme + 1e-16f);
    float4 cb4 = ((const float4*)cb)[lane];
    float4 ga  = ((const float4*)g_gamma)[i * 32 + lane];
    float4 be  = ((const float4*)g_beta)[i * 32 + lane];
    float y0 = ga.x * (acc.x * inv + cb4.x) + be.x;
    float y1 = ga.y * (acc.y * inv + cb4.y) + be.y;
    float y2 = ga.z * (acc.z * inv + cb4.z) + be.z;
    float y3 = ga.w * (acc.w * inv + cb4.w) + be.w;
    float s1 = y0 + y1 + y2 + y3;
    float s2 = y0*y0 + y1*y1 + y2*y2 + y3*y3;
    #pragma unroll
    for (int o = 16; o > 0; o >>= 1) {
        s1 += __shfl_xor_sync(0xFFFFFFFFu, s1, o);
        s2 += __shfl_xor_sync(0xFFFFFFFFu, s2, o);
    }
    float mean = s1 * (1.0f / 128.0f);
    float var  = s2 * (1.0f / 128.0f) - mean * mean;
    float ivs  = rsqrtf(var + 1e-5f);
    float4 g4 = ((const float4*)lng)[lane];
    float4 b4 = ((const float4*)lnb)[lane];
    float4 ho = ((const float4*)g_h)[i * 32 + lane];
    float4 out;
    out.x = gelu_f((y0 - mean) * ivs * g4.x + b4.x) + ho.x;
    out.y = gelu_f((y1 - mean) * ivs * g4.y + b4.y) + ho.y;
    out.z = gelu_f((y2 - mean) * ivs * g4.z + b4.z) + ho.z;
    out.w = gelu_f((y3 - mean) * ivs * g4.w + b4.w) + ho.w;
    ((float4*)g_h)[i * 32 + lane] = out;
}

// ---------------- decoder + mask + output (+ reset counters for next replay) ----------------
__global__ void k_dec(const float* __restrict__ W1, const float* __restrict__ b1,
                      const float* __restrict__ W2, const float* __restrict__ b2,
                      const float* __restrict__ x, const void* __restrict__ mask,
                      float* __restrict__ out, int n, int out_size) {
    __shared__ float sW1[8192];
    __shared__ float sW2[128];
    __shared__ float sb1v[64];
    __shared__ float sb2v[2];
    __shared__ float sH[8][128];
    int tid = threadIdx.x;
    // reset CSR counters / flags for next graph replay
    int gid = blockIdx.x * blockDim.x + tid;
    if (gid < n) g_cnt[gid] = 0;
    if (gid < 2) g_viol[gid] = 0;
    for (int i = tid; i < 8192; i += 256) sW1[i] = W1[i];
    if (tid < 128) sW2[tid] = W2[tid];
    if (tid < 64) sb1v[tid] = b1[tid];
    if (tid < 2) sb2v[tid] = b2[tid];
    __syncthreads();
    int warp = tid >> 5, lane = tid & 31;
    int mode = g_maskmode;
    for (int i = blockIdx.x * 8 + warp; i < n; i += gridDim.x * 8) {
        #pragma unroll
        for (int h = 0; h < 4; h++) sH[warp][h * 32 + lane] = g_h[i * 128 + h * 32 + lane];
        __syncwarp();
        float a0 = sb1v[lane], a1 = sb1v[lane + 32];
        for (int k = 0; k < 128; k++) {
            float hv = sH[warp][k];
            a0 += hv * sW1[k * 64 + lane];
            a1 += hv * sW1[k * 64 + lane + 32];
        }
        float t0 = gelu_f(a0), t1 = gelu_f(a1);
        float d0 = t0 * sW2[lane * 2]     + t1 * sW2[(lane + 32) * 2];
        float d1 = t0 * sW2[lane * 2 + 1] + t1 * sW2[(lane + 32) * 2 + 1];
        #pragma unroll
        for (int o = 16; o > 0; o >>= 1) {
            d0 += __shfl_xor_sync(0xFFFFFFFFu, d0, o);
            d1 += __shfl_xor_sync(0xFFFFFFFFu, d1, o);
        }
        if (lane == 0) {
            d0 += sb2v[0]; d1 += sb2v[1];
            int fixed;
            if (mode == 0)      fixed = ((const int*)mask)[i] != 0;
            else if (mode == 1) fixed = ((const float*)mask)[i] != 0.f;
            else                fixed = ((const unsigned char*)mask)[i] != 0;
            if (fixed) { d0 = 0.f; d1 = 0.f; }
            out[i * 2]     = x[i * 6]     + d0;
            out[i * 2 + 1] = x[i * 6 + 1] + d1;
            if (out_size >= 4 * n) {
                out[2 * n + i * 2]     = d0;
                out[2 * n + i * 2 + 1] = d1;
            }
        }
        __syncwarp();
    }
}

// ---------------- launch ----------------
extern "C" void kernel_launch(void* const* d_in, const int* in_sizes, int n_in,
                              void* d_out, int out_size) {
    const float* x    = (const float*)d_in[0];
    const int*   ei   = (const int*)d_in[1];
    const float* ea   = (const float*)d_in[2];
    const float* tmp  = (const float*)d_in[3];
    const void*  mask = d_in[4];
    const float* encW = (const float*)d_in[5];
    const float* encB = (const float*)d_in[6];
    const float* encG = (const float*)d_in[7];
    const float* encBe= (const float*)d_in[8];
    const float* fW1  = (const float*)d_in[9];
    const float* fb1  = (const float*)d_in[10];
    const float* fW2  = (const float*)d_in[11];
    const float* fb2  = (const float*)d_in[12];
    const float* Wl   = (const float*)d_in[13];
    const float* bl   = (const float*)d_in[14];
    const float* Wr   = (const float*)d_in[15];
    const float* br   = (const float*)d_in[16];
    const float* We   = (const float*)d_in[17];
    const float* att  = (const float*)d_in[18];
    const float* cb   = (const float*)d_in[19];
    const float* lng  = (const float*)d_in[20];
    const float* lnb  = (const float*)d_in[21];
    const float* dW1  = (const float*)d_in[22];
    const float* db1  = (const float*)d_in[23];
    const float* dW2  = (const float*)d_in[24];
    const float* db2  = (const float*)d_in[25];
    float* out = (float*)d_out;

    int n = in_sizes[0] / 6;
    int e = in_sizes[2] / 4;

    cudaFuncSetAttribute(k_prep, cudaFuncAttributeMaxDynamicSharedMemorySize, 73728);
    cudaFuncSetAttribute(k_gemm, cudaFuncAttributeMaxDynamicSharedMemorySize, 196608);

    // launches: count(1), scan(2), prep(3), gemm0(4) <- profiled, scatter(5), ...
    k_count<<<(e + 255) / 256, 256>>>(ei, (const int*)mask, e, n);
    k_scan<<<1, 1024>>>(n);
    k_prep<<<592, 256, 72192>>>(x, tmp, encW, encB, encG, encBe,
                                fW1, fb1, fW2, fb2, n);
    k_gemm<<<(n + 127) / 128, 512, 196608>>>(Wl, bl, Wr, br, n);
    k_scatter<<<(e + 255) / 256, 256>>>(ei, (const float4*)ea, e);
    k_node<<<(n + 7) / 8, 256>>>(We, att, cb, lng, lnb, n);

    for (int l = 1; l < 4; l++) {
        k_gemm<<<(n + 127) / 128, 512, 196608>>>(Wl + l * 16384, bl + l * 128,
                                                 Wr + l * 16384, br + l * 128, n);
        k_node<<<(n + 7) / 8, 256>>>(We + l * 512, att + l * 128,
                                     cb + l * 128, lng + l * 128, lnb + l * 128, n);
    }

    // decoder + output (+ counter reset for next replay)
    k_dec<<<1536, 256>>>(dW1, db1, dW2, db2, x, mask, out, n, out_size);
}

// round 5
// speedup vs baseline: 2.0350x; 1.0061x over previous
#include <cuda_runtime.h>
#include <cuda_fp16.h>
#include <math.h>

#define HID 128
#define NMAX 50048
#define EMAX 1600000

// ---------------- device scratch ----------------
__device__ float   g_h[NMAX * HID];       // fp32 h (residual + decoder)
__device__ __half  g_hh[NMAX * HID];      // fp16 h (GEMM input)
__device__ __half2 g_xlh[NMAX * 64];      // xl fp16 (gather payload)
__device__ float   g_xr[NMAX * HID];
__device__ float   g_gamma[NMAX * HID];
__device__ float   g_beta[NMAX * HID];
__device__ float4  g_ea[EMAX];
__device__ int     g_off[NMAX + 1];
__device__ int     g_cnt[NMAX];           // zero-init at load; re-zeroed by k_dec
__device__ int     g_csrc[EMAX];
__device__ int     g_viol[2];
__device__ int     g_maskmode;

__device__ __forceinline__ float gelu_f(float x) {
    return 0.5f * x * (1.0f + erff(x * 0.7071067811865476f));
}

// ---------------- CSR build ----------------
__global__ void k_count(const int* ei, const int* m, int e, int n) {
    int i = blockIdx.x * blockDim.x + threadIdx.x;
    if (i < e) atomicAdd(&g_cnt[ei[e + i]], 1);
    int words = n >> 2;
    int lim = words < 8192 ? words : 8192;
    if (i < lim) {
        int v = m[i];
        if (v != 0 && v != 1) atomicOr(&g_viol[0], 1);
        if (v != 0 && v != 0x3F800000) atomicOr(&g_viol[1], 1);
    }
}

__global__ void k_scan(int n) {
    __shared__ int warpsum[32];
    int t = threadIdx.x;
    int per = (n + 1023) >> 10;
    int i0 = t * per;
    int i1 = i0 + per; if (i1 > n) i1 = n; if (i0 > n) i0 = n;
    int local = 0;
    for (int i = i0; i < i1; i++) local += g_cnt[i];
    int lane = t & 31, warp = t >> 5;
    int v = local;
    #pragma unroll
    for (int o = 1; o < 32; o <<= 1) {
        int u = __shfl_up_sync(0xFFFFFFFFu, v, o);
        if (lane >= o) v += u;
    }
    if (lane == 31) warpsum[warp] = v;
    __syncthreads();
    if (warp == 0) {
        int w = warpsum[lane];
        #pragma unroll
        for (int o = 1; o < 32; o <<= 1) {
            int u = __shfl_up_sync(0xFFFFFFFFu, w, o);
            if (lane >= o) w += u;
        }
        warpsum[lane] = w;
    }
    __syncthreads();
    int excl = v - local + (warp ? warpsum[warp - 1] : 0);
    int run = excl;
    for (int i = i0; i < i1; i++) {
        int c = g_cnt[i];
        g_off[i] = run;
        g_cnt[i] = run;
        run += c;
    }
    if (t == 1023) g_off[n] = run;
    if (t == 0) g_maskmode = (g_viol[0] == 0) ? 0 : ((g_viol[1] == 0) ? 1 : 2);
}

__global__ void k_scatter(const int* ei, const float4* __restrict__ ea, int e) {
    int i = blockIdx.x * blockDim.x + threadIdx.x;
    if (i >= e) return;
    int s = ei[i], d = ei[e + i];
    int pos = atomicAdd(&g_cnt[d], 1);
    g_csrc[pos] = s;
    g_ea[pos] = ea[i];
}

// ---------------- encoder + FiLM (one warp per node) ----------------
__global__ void k_prep(const float* __restrict__ x, const float* __restrict__ tmp,
                       const float* __restrict__ encW, const float* __restrict__ encB,
                       const float* __restrict__ encG, const float* __restrict__ encBe,
                       const float* __restrict__ fW1, const float* __restrict__ fb1,
                       const float* __restrict__ fW2, const float* __restrict__ fb2,
                       int n) {
    extern __shared__ float sm[];
    float* sEncW = sm;            // 768
    float* sW1   = sm + 768;      // 64
    float* sB1   = sm + 832;      // 64
    float* sB2   = sm + 896;      // 256
    float* sW2   = sm + 1152;     // 16384
    float* sT1   = sm + 17536;    // 512
    int tid = threadIdx.x;
    for (int i = tid; i < 768; i += blockDim.x) sEncW[i] = encW[i];
    for (int i = tid; i < 64; i += blockDim.x) { sW1[i] = fW1[i]; sB1[i] = fb1[i]; }
    for (int i = tid; i < 256; i += blockDim.x) sB2[i] = fb2[i];
    for (int i = tid; i < 4096; i += blockDim.x)
        ((float4*)sW2)[i] = ((const float4*)fW2)[i];
    __syncthreads();
    int warp = tid >> 5, lane = tid & 31;
    for (int i = blockIdx.x * 8 + warp; i < n; i += gridDim.x * 8) {
        float xv[6];
        #pragma unroll
        for (int j = 0; j < 6; j++) xv[j] = x[i * 6 + j];
        float y[4];
        #pragma unroll
        for (int h = 0; h < 4; h++) {
            int k = h * 32 + lane;
            float a = encB[k];
            #pragma unroll
            for (int j = 0; j < 6; j++) a += xv[j] * sEncW[j * 128 + k];
            y[h] = a;
        }
        float s1 = y[0] + y[1] + y[2] + y[3];
        float s2 = y[0]*y[0] + y[1]*y[1] + y[2]*y[2] + y[3]*y[3];
        #pragma unroll
        for (int o = 16; o > 0; o >>= 1) {
            s1 += __shfl_xor_sync(0xFFFFFFFFu, s1, o);
            s2 += __shfl_xor_sync(0xFFFFFFFFu, s2, o);
        }
        float mean = s1 * (1.0f / 128.0f);
        float var  = s2 * (1.0f / 128.0f) - mean * mean;
        float inv  = rsqrtf(var + 1e-5f);
        #pragma unroll
        for (int h = 0; h < 4; h++) {
            int k = h * 32 + lane;
            float v = (y[h] - mean) * inv * encG[k] + encBe[k];
            float g = gelu_f(v);
            g_h[i * 128 + k]  = g;
            g_hh[i * 128 + k] = __float2half_rn(g);
        }
        float tm = tmp[i];
        #pragma unroll
        for (int c = 0; c < 2; c++) {
            int j = lane + 32 * c;
            sT1[warp * 64 + j] = gelu_f(tm * sW1[j] + sB1[j]);
        }
        __syncwarp();
        float f[8];
        #pragma unroll
        for (int c = 0; c < 8; c++) f[c] = sB2[lane + 32 * c];
        for (int j = 0; j < 64; j++) {
            float t = sT1[warp * 64 + j];
            #pragma unroll
            for (int c = 0; c < 8; c++) f[c] += t * sW2[j * 256 + lane + 32 * c];
        }
        #pragma unroll
        for (int c = 0; c < 4; c++) {
            g_gamma[i * 128 + lane + 32 * c] = f[c];
            g_beta[i * 128 + lane + 32 * c]  = f[c + 4];
        }
        __syncwarp();
    }
}

// ---------------- tensor-core dual GEMM: xl(fp16) = h@Wl+bl, xr(fp32) = h@Wr+br ----------------
// fp16 mma.sync m16n8k16, fp32 accumulate. A = g_hh [128 rows x 128k], B = [Wl|Wr] as [256n x 128k] fp16.
#define AST 136   // padded k-stride (halfs)
__global__ void __launch_bounds__(512, 1)
k_gemm(const float* __restrict__ Wl, const float* __restrict__ blv,
       const float* __restrict__ Wr, const float* __restrict__ brv, int n) {
    extern __shared__ __half smh[];
    __half* As = smh;               // 128 x 136
    __half* Bs = smh + 128 * AST;   // 256 x 136
    int tid = threadIdx.x;
    int row0 = blockIdx.x * 128;

    // load A (fp16 h rows) : 128 rows x 128 halfs, uint4 = 8 halfs
    for (int idx = tid; idx < 2048; idx += 512) {
        int row = idx >> 4, c8 = idx & 15;
        int gr = row0 + row;
        uint4 v = make_uint4(0, 0, 0, 0);
        if (gr < n) v = ((const uint4*)g_hh)[gr * 16 + c8];
        *(uint4*)&As[row * AST + c8 * 8] = v;
    }
    // load B transposed to [n][k] fp16: n<128 from Wl, else Wr
    for (int idx = tid; idx < 32768; idx += 512) {
        int nn = idx & 255, kk = idx >> 8;
        float v = (nn < 128) ? Wl[kk * 128 + nn] : Wr[kk * 128 + nn - 128];
        Bs[nn * AST + kk] = __float2half_rn(v);
    }
    __syncthreads();

    int warp = tid >> 5, lane = tid & 31;
    int mi = warp & 3, ni = warp >> 2;       // m-tile (32 rows), n-tile (64 cols)
    int gid = lane >> 2, tig = lane & 3;

    float d[2][8][4];
    #pragma unroll
    for (int tm = 0; tm < 2; tm++)
        #pragma unroll
        for (int tn = 0; tn < 8; tn++)
            #pragma unroll
            for (int q = 0; q < 4; q++) d[tm][tn][q] = 0.f;

    #pragma unroll
    for (int ks = 0; ks < 8; ks++) {
        int k0 = ks * 16;
        unsigned a[2][4];
        #pragma unroll
        for (int tm = 0; tm < 2; tm++) {
            int r = mi * 32 + tm * 16 + gid;
            a[tm][0] = *(const unsigned*)&As[r * AST + k0 + tig * 2];
            a[tm][1] = *(const unsigned*)&As[(r + 8) * AST + k0 + tig * 2];
            a[tm][2] = *(const unsigned*)&As[r * AST + k0 + tig * 2 + 8];
            a[tm][3] = *(const unsigned*)&As[(r + 8) * AST + k0 + tig * 2 + 8];
        }
        unsigned b[8][2];
        #pragma unroll
        for (int tn = 0; tn < 8; tn++) {
            int nn = ni * 64 + tn * 8 + gid;
            b[tn][0] = *(const unsigned*)&Bs[nn * AST + k0 + tig * 2];
            b[tn][1] = *(const unsigned*)&Bs[nn * AST + k0 + tig * 2 + 8];
        }
        #pragma unroll
        for (int tm = 0; tm < 2; tm++)
            #pragma unroll
            for (int tn = 0; tn < 8; tn++) {
                asm volatile(
                    "mma.sync.aligned.m16n8k16.row.col.f32.f16.f16.f32 "
                    "{%0,%1,%2,%3}, {%4,%5,%6,%7}, {%8,%9}, {%0,%1,%2,%3};\n"
                    : "+f"(d[tm][tn][0]), "+f"(d[tm][tn][1]),
                      "+f"(d[tm][tn][2]), "+f"(d[tm][tn][3])
                    : "r"(a[tm][0]), "r"(a[tm][1]), "r"(a[tm][2]), "r"(a[tm][3]),
                      "r"(b[tn][0]), "r"(b[tn][1]));
            }
    }

    // epilogue: bias + store (xl fp16 / xr fp32)
    #pragma unroll
    for (int tn = 0; tn < 8; tn++) {
        int nglob = ni * 64 + tn * 8 + tig * 2;
        float b0, b1;
        if (nglob < 128) { b0 = blv[nglob]; b1 = blv[nglob + 1]; }
        else             { b0 = brv[nglob - 128]; b1 = brv[nglob - 127]; }
        #pragma unroll
        for (int tm = 0; tm < 2; tm++) {
            int r0 = row0 + mi * 32 + tm * 16 + gid;
            int r1 = r0 + 8;
            float v0 = d[tm][tn][0] + b0, v1 = d[tm][tn][1] + b1;
            float v2 = d[tm][tn][2] + b0, v3 = d[tm][tn][3] + b1;
            if (nglob < 128) {
                if (r0 < n) g_xlh[r0 * 64 + (nglob >> 1)] = __floats2half2_rn(v0, v1);
                if (r1 < n) g_xlh[r1 * 64 + (nglob >> 1)] = __floats2half2_rn(v2, v3);
            } else {
                int c = nglob - 128;
                if (r0 < n) *(float2*)&g_xr[r0 * 128 + c] = make_float2(v0, v1);
                if (r1 < n) *(float2*)&g_xr[r1 * 128 + c] = make_float2(v2, v3);
            }
        }
    }
}

// ---- fused: edge scores + softmax (no-max, exact ratios) + aggregation + FiLM + LN + GELU + residual ----
// one warp per node; lane owns channels 4l..4l+3; 8 edges per iteration (MLP=8)
__global__ void __launch_bounds__(256, 2)
k_node(const float* __restrict__ We, const float* __restrict__ att,
       const float* __restrict__ cb, const float* __restrict__ lng,
       const float* __restrict__ lnb, int n) {
    int tid = threadIdx.x;
    int warp = tid >> 5, lane = tid & 31;
    int i = blockIdx.x * 8 + warp;
    if (i >= n) return;

    float4 we0 = ((const float4*)We)[lane];
    float4 we1 = ((const float4*)We)[32 + lane];
    float4 we2 = ((const float4*)We)[64 + lane];
    float4 we3 = ((const float4*)We)[96 + lane];
    float4 at  = ((const float4*)att)[lane];
    float4 xr  = ((const float4*)g_xr)[i * 32 + lane];

    int beg = g_off[i], end = g_off[i + 1];
    float sme = 0.f;
    float4 acc = make_float4(0.f, 0.f, 0.f, 0.f);
    const uint2* xlh = (const uint2*)g_xlh;

    for (int j = beg; j < end; j += 8) {
        int c = end - j;
        int s[8]; float4 ev[8]; uint2 rv[8];
        #pragma unroll
        for (int m = 0; m < 8; m++) {
            int jm = j + ((m < c) ? m : 0);
            s[m] = g_csrc[jm];
            ev[m] = g_ea[jm];
        }
        #pragma unroll
        for (int m = 0; m < 8; m++) rv[m] = xlh[s[m] * 32 + lane];

        float p[8]; float4 xv[8];
        #pragma unroll
        for (int m = 0; m < 8; m++) {
            float2 lo = __half22float2(*(__half2*)&rv[m].x);
            float2 hi = __half22float2(*(__half2*)&rv[m].y);
            xv[m] = make_float4(lo.x, lo.y, hi.x, hi.y);
            float4 ee = ev[m];
            float m0 = xv[m].x + xr.x + ee.x*we0.x + ee.y*we1.x + ee.z*we2.x + ee.w*we3.x;
            float m1 = xv[m].y + xr.y + ee.x*we0.y + ee.y*we1.y + ee.z*we2.y + ee.w*we3.y;
            float m2 = xv[m].z + xr.z + ee.x*we0.z + ee.y*we1.z + ee.z*we2.z + ee.w*we3.z;
            float m3 = xv[m].w + xr.w + ee.x*we0.w + ee.y*we1.w + ee.z*we2.w + ee.w*we3.w;
            m0 = fmaxf(m0, 0.2f * m0);
            m1 = fmaxf(m1, 0.2f * m1);
            m2 = fmaxf(m2, 0.2f * m2);
            m3 = fmaxf(m3, 0.2f * m3);
            p[m] = m0*at.x + m1*at.y + m2*at.z + m3*at.w;
        }
        #pragma unroll
        for (int o = 1; o < 8; o <<= 1) {
            #pragma unroll
            for (int m = 0; m < 8; m++)
                p[m] += __shfl_xor_sync(0xFFFFFFFFu, p[m], o);
        }
        #pragma unroll
        for (int m = 0; m < 8; m++) {
            float w = (m < c) ? __expf(p[m]) : 0.f;
            sme += w;
            acc.x += w * xv[m].x;
            acc.y += w * xv[m].y;
            acc.z += w * xv[m].z;
            acc.w += w * xv[m].w;
        }
    }

    float inv = 1.0f / (sme + 1e-16f);
    float4 cb4 = ((const float4*)cb)[lane];
    float4 ga  = ((const float4*)g_gamma)[i * 32 + lane];
    float4 be  = ((const float4*)g_beta)[i * 32 + lane];
    float y0 = ga.x * (acc.x * inv + cb4.x) + be.x;
    float y1 = ga.y * (acc.y * inv + cb4.y) + be.y;
    float y2 = ga.z * (acc.z * inv + cb4.z) + be.z;
    float y3 = ga.w * (acc.w * inv + cb4.w) + be.w;
    float s1 = y0 + y1 + y2 + y3;
    float s2 = y0*y0 + y1*y1 + y2*y2 + y3*y3;
    #pragma unroll
    for (int o = 16; o > 0; o >>= 1) {
        s1 += __shfl_xor_sync(0xFFFFFFFFu, s1, o);
        s2 += __shfl_xor_sync(0xFFFFFFFFu, s2, o);
    }
    float mean = s1 * (1.0f / 128.0f);
    float var  = s2 * (1.0f / 128.0f) - mean * mean;
    float ivs  = rsqrtf(var + 1e-5f);
    float4 g4 = ((const float4*)lng)[lane];
    float4 b4 = ((const float4*)lnb)[lane];
    float4 ho = ((const float4*)g_h)[i * 32 + lane];
    float4 out;
    out.x = gelu_f((y0 - mean) * ivs * g4.x + b4.x) + ho.x;
    out.y = gelu_f((y1 - mean) * ivs * g4.y + b4.y) + ho.y;
    out.z = gelu_f((y2 - mean) * ivs * g4.z + b4.z) + ho.z;
    out.w = gelu_f((y3 - mean) * ivs * g4.w + b4.w) + ho.w;
    ((float4*)g_h)[i * 32 + lane] = out;
    // fp16 copy for next layer's tensor-core GEMM
    __half2 o0 = __floats2half2_rn(out.x, out.y);
    __half2 o1 = __floats2half2_rn(out.z, out.w);
    uint2 pk;
    pk.x = *(unsigned*)&o0;
    pk.y = *(unsigned*)&o1;
    ((uint2*)g_hh)[i * 32 + lane] = pk;
}

// ---------------- decoder + mask + output (+ reset counters for next replay) ----------------
__global__ void k_dec(const float* __restrict__ W1, const float* __restrict__ b1,
                      const float* __restrict__ W2, const float* __restrict__ b2,
                      const float* __restrict__ x, const void* __restrict__ mask,
                      float* __restrict__ out, int n, int out_size) {
    __shared__ float sW1[8192];
    __shared__ float sW2[128];
    __shared__ float sb1v[64];
    __shared__ float sb2v[2];
    __shared__ float sH[8][128];
    int tid = threadIdx.x;
    int gid = blockIdx.x * blockDim.x + tid;
    if (gid < n) g_cnt[gid] = 0;
    if (gid < 2) g_viol[gid] = 0;
    for (int i = tid; i < 8192; i += 256) sW1[i] = W1[i];
    if (tid < 128) sW2[tid] = W2[tid];
    if (tid < 64) sb1v[tid] = b1[tid];
    if (tid < 2) sb2v[tid] = b2[tid];
    __syncthreads();
    int warp = tid >> 5, lane = tid & 31;
    int mode = g_maskmode;
    for (int i = blockIdx.x * 8 + warp; i < n; i += gridDim.x * 8) {
        #pragma unroll
        for (int h = 0; h < 4; h++) sH[warp][h * 32 + lane] = g_h[i * 128 + h * 32 + lane];
        __syncwarp();
        float a0 = sb1v[lane], a1 = sb1v[lane + 32];
        for (int k = 0; k < 128; k++) {
            float hv = sH[warp][k];
            a0 += hv * sW1[k * 64 + lane];
            a1 += hv * sW1[k * 64 + lane + 32];
        }
        float t0 = gelu_f(a0), t1 = gelu_f(a1);
        float d0 = t0 * sW2[lane * 2]     + t1 * sW2[(lane + 32) * 2];
        float d1 = t0 * sW2[lane * 2 + 1] + t1 * sW2[(lane + 32) * 2 + 1];
        #pragma unroll
        for (int o = 16; o > 0; o >>= 1) {
            d0 += __shfl_xor_sync(0xFFFFFFFFu, d0, o);
            d1 += __shfl_xor_sync(0xFFFFFFFFu, d1, o);
        }
        if (lane == 0) {
            d0 += sb2v[0]; d1 += sb2v[1];
            int fixed;
            if (mode == 0)      fixed = ((const int*)mask)[i] != 0;
            else if (mode == 1) fixed = ((const float*)mask)[i] != 0.f;
            else                fixed = ((const unsigned char*)mask)[i] != 0;
            if (fixed) { d0 = 0.f; d1 = 0.f; }
            out[i * 2]     = x[i * 6]     + d0;
            out[i * 2 + 1] = x[i * 6 + 1] + d1;
            if (out_size >= 4 * n) {
                out[2 * n + i * 2]     = d0;
                out[2 * n + i * 2 + 1] = d1;
            }
        }
        __syncwarp();
    }
}

// ---------------- launch ----------------
extern "C" void kernel_launch(void* const* d_in, const int* in_sizes, int n_in,
                              void* d_out, int out_size) {
    const float* x    = (const float*)d_in[0];
    const int*   ei   = (const int*)d_in[1];
    const float* ea   = (const float*)d_in[2];
    const float* tmp  = (const float*)d_in[3];
    const void*  mask = d_in[4];
    const float* encW = (const float*)d_in[5];
    const float* encB = (const float*)d_in[6];
    const float* encG = (const float*)d_in[7];
    const float* encBe= (const float*)d_in[8];
    const float* fW1  = (const float*)d_in[9];
    const float* fb1  = (const float*)d_in[10];
    const float* fW2  = (const float*)d_in[11];
    const float* fb2  = (const float*)d_in[12];
    const float* Wl   = (const float*)d_in[13];
    const float* bl   = (const float*)d_in[14];
    const float* Wr   = (const float*)d_in[15];
    const float* br   = (const float*)d_in[16];
    const float* We   = (const float*)d_in[17];
    const float* att  = (const float*)d_in[18];
    const float* cb   = (const float*)d_in[19];
    const float* lng  = (const float*)d_in[20];
    const float* lnb  = (const float*)d_in[21];
    const float* dW1  = (const float*)d_in[22];
    const float* db1  = (const float*)d_in[23];
    const float* dW2  = (const float*)d_in[24];
    const float* db2  = (const float*)d_in[25];
    float* out = (float*)d_out;

    int n = in_sizes[0] / 6;
    int e = in_sizes[2] / 4;

    const int gemm_smem = (128 * AST + 256 * AST) * 2;  // 104448
    cudaFuncSetAttribute(k_prep, cudaFuncAttributeMaxDynamicSharedMemorySize, 73728);
    cudaFuncSetAttribute(k_gemm, cudaFuncAttributeMaxDynamicSharedMemorySize, gemm_smem);

    // launches: count(0), scan(1), prep(2), gemm0(3) <- profiled, scatter(4), node0(5), ...
    k_count<<<(e + 255) / 256, 256>>>(ei, (const int*)mask, e, n);
    k_scan<<<1, 1024>>>(n);
    k_prep<<<592, 256, 72192>>>(x, tmp, encW, encB, encG, encBe,
                                fW1, fb1, fW2, fb2, n);
    k_gemm<<<(n + 127) / 128, 512, gemm_smem>>>(Wl, bl, Wr, br, n);
    k_scatter<<<(e + 255) / 256, 256>>>(ei, (const float4*)ea, e);
    k_node<<<(n + 7) / 8, 256>>>(We, att, cb, lng, lnb, n);

    for (int l = 1; l < 4; l++) {
        k_gemm<<<(n + 127) / 128, 512, gemm_smem>>>(Wl + l * 16384, bl + l * 128,
                                                    Wr + l * 16384, br + l * 128, n);
        k_node<<<(n + 7) / 8, 256>>>(We + l * 512, att + l * 128,
                                     cb + l * 128, lng + l * 128, lnb + l * 128, n);
    }

    k_dec<<<1536, 256>>>(dW1, db1, dW2, db2, x, mask, out, n, out_size);
}